// round 11
// baseline (speedup 1.0000x reference)
#include <cuda_runtime.h>
#include <cuda_bf16.h>
#include <math.h>
#include <stdint.h>

// Problem constants
#define B_SZ   4
#define L_SZ   1024
#define D_SZ   768
#define DI_SZ  1536
#define DI2_SZ 3072
#define N_ST   16
#define DTR_SZ 48
#define XDBL_W 80           // DTR + 2*N
#define M_ROWS 4096         // B*L
#define KSPLIT 4
#define XPART  (M_ROWS * XDBL_W)

// Scratch (device globals; no allocation allowed)
__device__ float g_xn  [M_ROWS * D_SZ];
__device__ float g_xz  [M_ROWS * DI2_SZ];
__device__ float g_xc  [M_ROWS * DI_SZ];
__device__ float g_xpart[KSPLIT * XPART];
__device__ float g_xdbl[M_ROWS * XDBL_W];
__device__ float g_delta[M_ROWS * DI_SZ];
__device__ float g_y   [M_ROWS * DI_SZ];

__device__ __forceinline__ void mma16(float* d,
                                      const uint32_t* a, const uint32_t* b) {
    asm volatile(
        "mma.sync.aligned.m16n8k16.row.col.f32.bf16.bf16.f32 "
        "{%0,%1,%2,%3}, {%4,%5,%6,%7}, {%8,%9}, {%0,%1,%2,%3};"
        : "+f"(d[0]), "+f"(d[1]), "+f"(d[2]), "+f"(d[3])
        : "r"(a[0]), "r"(a[1]), "r"(a[2]), "r"(a[3]), "r"(b[0]), "r"(b[1]));
}

__device__ __forceinline__ void ldsm4(uint32_t& r0, uint32_t& r1,
                                      uint32_t& r2, uint32_t& r3, uint32_t a) {
    asm volatile("ldmatrix.sync.aligned.m8n8.x4.shared.b16 {%0,%1,%2,%3}, [%4];"
                 : "=r"(r0), "=r"(r1), "=r"(r2), "=r"(r3) : "r"(a));
}

__device__ __forceinline__ uint32_t s2u(const void* p) {
    uint32_t a;
    asm("{ .reg .u64 t; cvta.to.shared.u64 t, %1; cvt.u32.u64 %0, t; }"
        : "=r"(a) : "l"(p));
    return a;
}

// split float4 into 4x bf16 hi (8B) and 4x bf16 lo (8B)
__device__ __forceinline__ void split4(float4 v, uint2& h, uint2& l) {
    __nv_bfloat16 hx = __float2bfloat16_rn(v.x);
    __nv_bfloat16 hy = __float2bfloat16_rn(v.y);
    __nv_bfloat16 hz = __float2bfloat16_rn(v.z);
    __nv_bfloat16 hw = __float2bfloat16_rn(v.w);
    __nv_bfloat162 h0 = __halves2bfloat162(hx, hy);
    __nv_bfloat162 h1 = __halves2bfloat162(hz, hw);
    __nv_bfloat162 l0 = __halves2bfloat162(
        __float2bfloat16_rn(v.x - __bfloat162float(hx)),
        __float2bfloat16_rn(v.y - __bfloat162float(hy)));
    __nv_bfloat162 l1 = __halves2bfloat162(
        __float2bfloat16_rn(v.z - __bfloat162float(hz)),
        __float2bfloat16_rn(v.w - __bfloat162float(hw)));
    h.x = *(uint32_t*)&h0; h.y = *(uint32_t*)&h1;
    l.x = *(uint32_t*)&l0; l.y = *(uint32_t*)&l1;
}

// hi-only pack: float4 -> 4x bf16 (8B)
__device__ __forceinline__ uint2 hi4(float4 v) {
    __nv_bfloat162 h0 = __floats2bfloat162_rn(v.x, v.y);
    __nv_bfloat162 h1 = __floats2bfloat162_rn(v.z, v.w);
    uint2 r;
    r.x = *(uint32_t*)&h0; r.y = *(uint32_t*)&h1;
    return r;
}

// ---------------------------------------------------------------------------
// LayerNorm: one block (256 thr) per row of 768
// ---------------------------------------------------------------------------
__global__ void ln_kernel(const float* __restrict__ x,
                          const float* __restrict__ gam,
                          const float* __restrict__ bet)
{
    int row = blockIdx.x;
    const float* xr = x + (size_t)row * D_SZ;
    float v[3];
    float s = 0.f, sq = 0.f;
#pragma unroll
    for (int i = 0; i < 3; i++) {
        v[i] = xr[threadIdx.x + i * 256];
        s += v[i];
        sq += v[i] * v[i];
    }
#pragma unroll
    for (int o = 16; o > 0; o >>= 1) {
        s  += __shfl_xor_sync(0xffffffffu, s, o);
        sq += __shfl_xor_sync(0xffffffffu, sq, o);
    }
    __shared__ float ss[8], ssq[8];
    int w = threadIdx.x >> 5, lane = threadIdx.x & 31;
    if (lane == 0) { ss[w] = s; ssq[w] = sq; }
    __syncthreads();
    if (w == 0) {
        s  = (lane < 8) ? ss[lane]  : 0.f;
        sq = (lane < 8) ? ssq[lane] : 0.f;
#pragma unroll
        for (int o = 4; o > 0; o >>= 1) {
            s  += __shfl_xor_sync(0xffffffffu, s, o);
            sq += __shfl_xor_sync(0xffffffffu, sq, o);
        }
        if (lane == 0) { ss[0] = s; ssq[0] = sq; }
    }
    __syncthreads();
    float mu  = ss[0] * (1.f / D_SZ);
    float var = ssq[0] * (1.f / D_SZ) - mu * mu;
    float rs  = rsqrtf(var + 1e-6f);
#pragma unroll
    for (int i = 0; i < 3; i++) {
        int c = threadIdx.x + i * 256;
        g_xn[(size_t)row * D_SZ + c] = (v[i] - mu) * rs * gam[c] + bet[c];
    }
}

// ---------------------------------------------------------------------------
// bf16-split NT GEMM, K-chunk 64: inline f32->bf16 hi/lo split at STS,
// ldmatrix mainloop.  Tile 128x128x64, 512 threads (16 warps 4x4),
// warp tile 32x32.  NPASS=3: full (err ~5e-7)  NPASS=2: drop hi*lo (~5e-6)
// EPI 0: plain   EPI 1: softplus(acc + bias[n])   EPI 2: relu(acc)+resid
// ---------------------------------------------------------------------------
#define RSB    144                // smem bytes per row (128 data + 16 pad)
#define TILEB  (128 * RSB)        // 18432
#define GSMEM2 (2 * 3 * TILEB)    // 110592 (2-pass: Ahi, Alo, Bhi)
#define GSMEM3 (2 * 4 * TILEB)    // 147456 (3-pass: + Blo)

template <int EPI, int NPASS>
__global__ __launch_bounds__(512)
void mgemm(const float* __restrict__ A, int lda,
           const float* __restrict__ Bm, int ldb,
           float* __restrict__ C, int M, int N, int K,
           const float* __restrict__ bias,
           const float* __restrict__ resid, size_t zC)
{
    constexpr int STG = (NPASS == 3 ? 4 : 3) * TILEB;
    extern __shared__ __align__(16) char smraw[];
    uint32_t smbase = s2u(smraw);

    A += (size_t)blockIdx.z * K;
    C += (size_t)blockIdx.z * zC;

    int tid = threadIdx.x;
    int wid = tid >> 5, lane = tid & 31;
    int wm = (wid & 3) * 32;
    int wn = (wid >> 2) * 32;
    int grp = lane >> 2, qd = lane & 3;
    int row0 = blockIdx.y * 128, col0 = blockIdx.x * 128;

    float acc[2][4][4];
#pragma unroll
    for (int mi = 0; mi < 2; mi++)
#pragma unroll
        for (int ni = 0; ni < 4; ni++)
#pragma unroll
            for (int e = 0; e < 4; e++) acc[mi][ni][e] = 0.f;

    const int nch = (K + 63) / 64;

    int lrow = tid >> 2;           // 0..127
    int q    = tid & 3;            // 16-float column group

    float4 pa[4], pb[4];

    auto loadc = [&](int c) {
        int kc = c * 64;
#pragma unroll
        for (int j = 0; j < 4; j++) {
            int col = kc + q * 16 + j * 4;
            bool kok = col < K;
            pa[j] = kok ? *(const float4*)(A + (size_t)(row0 + lrow) * lda + col)
                        : make_float4(0.f, 0.f, 0.f, 0.f);
            int n = col0 + lrow;
            pb[j] = (kok && n < N) ? *(const float4*)(Bm + (size_t)n * ldb + col)
                                   : make_float4(0.f, 0.f, 0.f, 0.f);
        }
    };

    auto storec = [&](int s) {
        uint32_t st = (uint32_t)s * STG + lrow * RSB;
#pragma unroll
        for (int j = 0; j < 4; j++) {
            uint32_t co = q * 32 + j * 8;    // byte col (bf16)
            uint2 h, l;
            split4(pa[j], h, l);             // A always hi+lo
            *(uint2*)(smraw + st + co)             = h;
            *(uint2*)(smraw + st + TILEB + co)     = l;
            if (NPASS == 3) {
                split4(pb[j], h, l);
                *(uint2*)(smraw + st + 2 * TILEB + co) = h;
                *(uint2*)(smraw + st + 3 * TILEB + co) = l;
            } else {
                *(uint2*)(smraw + st + 2 * TILEB + co) = hi4(pb[j]);
            }
        }
    };

    loadc(0);
    storec(0);
    __syncthreads();

    int arow = lane & 15;
    int asel = (lane >> 4) * 16;
    int brow = ((lane >> 4) << 3) + (lane & 7);
    int bsel = ((lane >> 3) & 1) * 16;

    for (int c = 0; c < nch; c++) {
        int s = c & 1;
        if (c + 1 < nch) loadc(c + 1);

        uint32_t stA  = smbase + (uint32_t)s * STG;
        uint32_t stAl = stA + TILEB;
        uint32_t stB  = stA + 2 * TILEB;
        uint32_t stBl = stA + 3 * TILEB;

#pragma unroll
        for (int ks = 0; ks < 4; ks++) {
            int kb = ks * 32;   // byte offset of k-16 group
            uint32_t ahi[2][4], alo[2][4], bhi[4][2], blo[4][2];
#pragma unroll
            for (int mi = 0; mi < 2; mi++) {
                uint32_t ad = stA + (wm + mi * 16 + arow) * RSB + kb + asel;
                ldsm4(ahi[mi][0], ahi[mi][1], ahi[mi][2], ahi[mi][3], ad);
            }
#pragma unroll
            for (int nb = 0; nb < 2; nb++) {
                uint32_t bd = stB + (wn + nb * 16 + brow) * RSB + kb + bsel;
                ldsm4(bhi[2 * nb][0], bhi[2 * nb][1],
                      bhi[2 * nb + 1][0], bhi[2 * nb + 1][1], bd);
            }
            // pass 1: hi*hi
#pragma unroll
            for (int mi = 0; mi < 2; mi++)
#pragma unroll
                for (int ni = 0; ni < 4; ni++)
                    mma16(acc[mi][ni], ahi[mi], bhi[ni]);
            // pass 2: lo*hi
#pragma unroll
            for (int mi = 0; mi < 2; mi++) {
                uint32_t ad = stAl + (wm + mi * 16 + arow) * RSB + kb + asel;
                ldsm4(alo[mi][0], alo[mi][1], alo[mi][2], alo[mi][3], ad);
            }
#pragma unroll
            for (int mi = 0; mi < 2; mi++)
#pragma unroll
                for (int ni = 0; ni < 4; ni++)
                    mma16(acc[mi][ni], alo[mi], bhi[ni]);
            // pass 3: hi*lo (full precision only)
            if (NPASS == 3) {
#pragma unroll
                for (int nb = 0; nb < 2; nb++) {
                    uint32_t bd = stBl + (wn + nb * 16 + brow) * RSB + kb + bsel;
                    ldsm4(blo[2 * nb][0], blo[2 * nb][1],
                          blo[2 * nb + 1][0], blo[2 * nb + 1][1], bd);
                }
#pragma unroll
                for (int mi = 0; mi < 2; mi++)
#pragma unroll
                    for (int ni = 0; ni < 4; ni++)
                        mma16(acc[mi][ni], ahi[mi], blo[ni]);
            }
        }

        if (c + 1 < nch) storec((c + 1) & 1);
        __syncthreads();
    }

    // epilogue: registers -> gmem
#pragma unroll
    for (int mi = 0; mi < 2; mi++) {
#pragma unroll
        for (int ni = 0; ni < 4; ni++) {
            int r  = row0 + wm + mi * 16 + grp;
            int cc = col0 + wn + ni * 8 + qd * 2;
            if (cc < N) {
#pragma unroll
                for (int h = 0; h < 2; h++) {
                    int rr = r + h * 8;
                    float v0 = acc[mi][ni][h * 2 + 0];
                    float v1 = acc[mi][ni][h * 2 + 1];
                    if (EPI == 1) {
                        v0 += bias[cc];
                        v1 += bias[cc + 1];
                        v0 = (v0 > 20.f) ? v0 : log1pf(__expf(v0));
                        v1 = (v1 > 20.f) ? v1 : log1pf(__expf(v1));
                    } else if (EPI == 2) {
                        v0 = fmaxf(v0, 0.f) + resid[(size_t)rr * N + cc];
                        v1 = fmaxf(v1, 0.f) + resid[(size_t)rr * N + cc + 1];
                    }
                    float2 o; o.x = v0; o.y = v1;
                    *(float2*)(C + (size_t)rr * N + cc) = o;
                }
            }
        }
    }
}

// ---------------------------------------------------------------------------
// Reduce split-K partials for x_dbl
// ---------------------------------------------------------------------------
__global__ void xdbl_reduce_kernel()
{
    int i = blockIdx.x * 256 + threadIdx.x;
    if (i < XPART) {
        float s = g_xpart[i] + g_xpart[i + XPART]
                + g_xpart[i + 2 * XPART] + g_xpart[i + 3 * XPART];
        g_xdbl[i] = s;
    }
}

// ---------------------------------------------------------------------------
// Causal depthwise conv (width 4) + bias + SiLU; 4 outputs per thread.
// ---------------------------------------------------------------------------
__global__ void conv_silu_kernel(const float* __restrict__ Wc,
                                 const float* __restrict__ bc)
{
    int gid = blockIdx.x * blockDim.x + threadIdx.x;
    if (gid >= (M_ROWS / 4) * DI_SZ) return;
    int d   = gid % DI_SZ;
    int blk = gid / DI_SZ;
    int b   = blk / (L_SZ / 4);
    int l0  = (blk % (L_SZ / 4)) * 4;
    int bl0 = b * L_SZ + l0;

    float w0 = Wc[d * 4 + 0], w1 = Wc[d * 4 + 1];
    float w2 = Wc[d * 4 + 2], w3 = Wc[d * 4 + 3];
    float bb = bc[d];

    float x[7];
#pragma unroll
    for (int k = 0; k < 7; k++) {
        int l = l0 - 3 + k;
        x[k] = (l >= 0) ? g_xz[(size_t)(bl0 - 3 + k) * DI2_SZ + d] : 0.f;
    }
#pragma unroll
    for (int i = 0; i < 4; i++) {
        float acc = bb;
        acc = fmaf(w0, x[i],     acc);
        acc = fmaf(w1, x[i + 1], acc);
        acc = fmaf(w2, x[i + 2], acc);
        acc = fmaf(w3, x[i + 3], acc);
        g_xc[(size_t)(bl0 + i) * DI_SZ + d] = acc / (1.f + __expf(-acc));
    }
}

// ---------------------------------------------------------------------------
// Selective scan + skip + gate, 4-step batched (R9 version).
// ---------------------------------------------------------------------------
__global__ __launch_bounds__(256)
void scan_kernel(const float* __restrict__ A_log,
                 const float* __restrict__ Dpar)
{
    int gtid  = blockIdx.x * 256 + threadIdx.x;
    int chain = gtid >> 4;          // 0..6143
    int n     = gtid & 15;
    int b     = chain / DI_SZ;
    int d     = chain % DI_SZ;

    float a  = -__expf(A_log[d * N_ST + n]);
    float dp = Dpar[d];
    float h  = 0.f;
    int base = b * L_SZ;

    const float* pd = g_delta + (size_t)base * DI_SZ + d;
    const float* pu = g_xc    + (size_t)base * DI_SZ + d;
    const float* px = g_xdbl  + (size_t)base * XDBL_W + DTR_SZ + n;
    const float* pz = g_xz    + (size_t)base * DI2_SZ + DI_SZ + d;
    float*       py = g_y     + (size_t)base * DI_SZ + d;

    float dl[4], u[4], Bv[4], Cv[4], z[4];
#pragma unroll
    for (int i = 0; i < 4; i++) {
        dl[i] = pd[i * DI_SZ];
        u[i]  = pu[i * DI_SZ];
        Bv[i] = px[i * XDBL_W];
        Cv[i] = px[i * XDBL_W + N_ST];
        z[i]  = pz[i * DI2_SZ];
    }
    pd += 4 * DI_SZ; pu += 4 * DI_SZ; px += 4 * XDBL_W; pz += 4 * DI2_SZ;

    for (int blk = 0; blk < L_SZ / 4; blk++) {
        float dl2[4], u2[4], Bv2[4], Cv2[4], z2[4];
        if (blk + 1 < L_SZ / 4) {
#pragma unroll
            for (int i = 0; i < 4; i++) {
                dl2[i] = pd[i * DI_SZ];
                u2[i]  = pu[i * DI_SZ];
                Bv2[i] = px[i * XDBL_W];
                Cv2[i] = px[i * XDBL_W + N_ST];
                z2[i]  = pz[i * DI2_SZ];
            }
            pd += 4 * DI_SZ; pu += 4 * DI_SZ; px += 4 * XDBL_W; pz += 4 * DI2_SZ;
        }

        float s0, s1, s2, s3;
        {
            float dA;
            dA = __expf(dl[0] * a); h = fmaf(dA, h, dl[0] * Bv[0] * u[0]); s0 = h * Cv[0];
            dA = __expf(dl[1] * a); h = fmaf(dA, h, dl[1] * Bv[1] * u[1]); s1 = h * Cv[1];
            dA = __expf(dl[2] * a); h = fmaf(dA, h, dl[2] * Bv[2] * u[2]); s2 = h * Cv[2];
            dA = __expf(dl[3] * a); h = fmaf(dA, h, dl[3] * Bv[3] * u[3]); s3 = h * Cv[3];
        }

#pragma unroll
        for (int o = 8; o > 0; o >>= 1) {
            s0 += __shfl_xor_sync(0xffffffffu, s0, o);
            s1 += __shfl_xor_sync(0xffffffffu, s1, o);
            s2 += __shfl_xor_sync(0xffffffffu, s2, o);
            s3 += __shfl_xor_sync(0xffffffffu, s3, o);
        }

        if (n == 0) {
            float sv[4] = {s0, s1, s2, s3};
#pragma unroll
            for (int i = 0; i < 4; i++) {
                float sil = z[i] / (1.f + __expf(-z[i]));
                py[i * DI_SZ] = (sv[i] + u[i] * dp) * sil;
            }
        }
        py += 4 * DI_SZ;

#pragma unroll
        for (int i = 0; i < 4; i++) {
            dl[i] = dl2[i]; u[i] = u2[i]; Bv[i] = Bv2[i]; Cv[i] = Cv2[i]; z[i] = z2[i];
        }
    }
}

// ---------------------------------------------------------------------------
extern "C" void kernel_launch(void* const* d_in, const int* in_sizes, int n_in,
                              void* d_out, int out_size)
{
    const float* input   = (const float*)d_in[0];
    const float* ln_g    = (const float*)d_in[1];
    const float* ln_b    = (const float*)d_in[2];
    const float* W_in    = (const float*)d_in[3];
    const float* W_conv  = (const float*)d_in[4];
    const float* b_conv  = (const float*)d_in[5];
    const float* W_x     = (const float*)d_in[6];
    const float* W_dt    = (const float*)d_in[7];
    const float* b_dt    = (const float*)d_in[8];
    const float* A_log   = (const float*)d_in[9];
    const float* D_param = (const float*)d_in[10];
    const float* W_out   = (const float*)d_in[11];
    float* out = (float*)d_out;

    float *xn, *xz, *xc, *xpart, *xdbl, *delta, *y;
    cudaGetSymbolAddress((void**)&xn,    g_xn);
    cudaGetSymbolAddress((void**)&xz,    g_xz);
    cudaGetSymbolAddress((void**)&xc,    g_xc);
    cudaGetSymbolAddress((void**)&xpart, g_xpart);
    cudaGetSymbolAddress((void**)&xdbl,  g_xdbl);
    cudaGetSymbolAddress((void**)&delta, g_delta);
    cudaGetSymbolAddress((void**)&y,     g_y);

    cudaFuncSetAttribute(mgemm<0,2>, cudaFuncAttributeMaxDynamicSharedMemorySize, GSMEM2);
    cudaFuncSetAttribute(mgemm<0,3>, cudaFuncAttributeMaxDynamicSharedMemorySize, GSMEM3);
    cudaFuncSetAttribute(mgemm<1,3>, cudaFuncAttributeMaxDynamicSharedMemorySize, GSMEM3);
    cudaFuncSetAttribute(mgemm<2,2>, cudaFuncAttributeMaxDynamicSharedMemorySize, GSMEM2);

    // 1. LayerNorm
    ln_kernel<<<M_ROWS, 256>>>(input, ln_g, ln_b);

    // 2. in-proj: xz = xn @ W_in^T   (4096 x 3072 x 768) — 2-pass
    {
        dim3 g(DI2_SZ / 128, M_ROWS / 128, 1);
        mgemm<0,2><<<g, 512, GSMEM2>>>(xn, D_SZ, W_in, D_SZ, xz,
                                       M_ROWS, DI2_SZ, D_SZ, nullptr, nullptr, 0);
    }

    // 3. causal depthwise conv + SiLU -> xc
    {
        int total = (M_ROWS / 4) * DI_SZ;
        conv_silu_kernel<<<(total + 255) / 256, 256>>>(W_conv, b_conv);
    }

    // 4. x_dbl = xc @ W_x^T   (4096 x 80 x 1536) — split-K x4, 3-pass
    {
        dim3 g(1, M_ROWS / 128, KSPLIT);
        mgemm<0,3><<<g, 512, GSMEM3>>>(xc, DI_SZ, W_x, DI_SZ, xpart,
                                       M_ROWS, XDBL_W, DI_SZ / KSPLIT,
                                       nullptr, nullptr, (size_t)XPART);
        xdbl_reduce_kernel<<<(XPART + 255) / 256, 256>>>();
    }

    // 5. delta = softplus(dt @ W_dt^T + b_dt)   (4096 x 1536 x 48) — 3-pass
    {
        dim3 g(DI_SZ / 128, M_ROWS / 128, 1);
        mgemm<1,3><<<g, 512, GSMEM3>>>(xdbl, XDBL_W, W_dt, DTR_SZ, delta,
                                       M_ROWS, DI_SZ, DTR_SZ, b_dt, nullptr, 0);
    }

    // 6. selective scan + skip + gating -> y
    {
        int threads = B_SZ * DI_SZ * N_ST;   // 98304
        scan_kernel<<<threads / 256, 256>>>(A_log, D_param);
    }

    // 7. out = relu(y @ W_out^T) + input   (4096 x 768 x 1536) — 2-pass
    {
        dim3 g(D_SZ / 128, M_ROWS / 128, 1);
        mgemm<2,2><<<g, 512, GSMEM2>>>(y, DI_SZ, W_out, DI_SZ, out,
                                       M_ROWS, D_SZ, DI_SZ, nullptr, input, 0);
    }
}

// round 12
// speedup vs baseline: 1.5650x; 1.5650x over previous
#include <cuda_runtime.h>
#include <cuda_bf16.h>
#include <math.h>
#include <stdint.h>

// Problem constants
#define B_SZ   4
#define L_SZ   1024
#define D_SZ   768
#define DI_SZ  1536
#define DI2_SZ 3072
#define N_ST   16
#define DTR_SZ 48
#define XDBL_W 80           // DTR + 2*N
#define M_ROWS 4096         // B*L
#define KSPLIT 4
#define XPART  (M_ROWS * XDBL_W)

// Scratch (device globals; no allocation allowed)
__device__ float g_xn  [M_ROWS * D_SZ];
__device__ float g_xz  [M_ROWS * DI2_SZ];
__device__ float g_xc  [M_ROWS * DI_SZ];
__device__ float g_xpart[KSPLIT * XPART];
__device__ float g_xdbl[M_ROWS * XDBL_W];
__device__ float g_delta[M_ROWS * DI_SZ];
__device__ float g_y   [M_ROWS * DI_SZ];

__device__ __forceinline__ void mma16(float* d,
                                      const uint32_t* a, const uint32_t* b) {
    asm volatile(
        "mma.sync.aligned.m16n8k16.row.col.f32.bf16.bf16.f32 "
        "{%0,%1,%2,%3}, {%4,%5,%6,%7}, {%8,%9}, {%0,%1,%2,%3};"
        : "+f"(d[0]), "+f"(d[1]), "+f"(d[2]), "+f"(d[3])
        : "r"(a[0]), "r"(a[1]), "r"(a[2]), "r"(a[3]), "r"(b[0]), "r"(b[1]));
}

__device__ __forceinline__ void ldsm4(uint32_t& r0, uint32_t& r1,
                                      uint32_t& r2, uint32_t& r3, uint32_t a) {
    asm volatile("ldmatrix.sync.aligned.m8n8.x4.shared.b16 {%0,%1,%2,%3}, [%4];"
                 : "=r"(r0), "=r"(r1), "=r"(r2), "=r"(r3) : "r"(a));
}

__device__ __forceinline__ uint32_t s2u(const void* p) {
    uint32_t a;
    asm("{ .reg .u64 t; cvta.to.shared.u64 t, %1; cvt.u32.u64 %0, t; }"
        : "=r"(a) : "l"(p));
    return a;
}

// split float4 into 4x bf16 hi (8B) and 4x bf16 lo (8B)
__device__ __forceinline__ void split4(float4 v, uint2& h, uint2& l) {
    __nv_bfloat16 hx = __float2bfloat16_rn(v.x);
    __nv_bfloat16 hy = __float2bfloat16_rn(v.y);
    __nv_bfloat16 hz = __float2bfloat16_rn(v.z);
    __nv_bfloat16 hw = __float2bfloat16_rn(v.w);
    __nv_bfloat162 h0 = __halves2bfloat162(hx, hy);
    __nv_bfloat162 h1 = __halves2bfloat162(hz, hw);
    __nv_bfloat162 l0 = __halves2bfloat162(
        __float2bfloat16_rn(v.x - __bfloat162float(hx)),
        __float2bfloat16_rn(v.y - __bfloat162float(hy)));
    __nv_bfloat162 l1 = __halves2bfloat162(
        __float2bfloat16_rn(v.z - __bfloat162float(hz)),
        __float2bfloat16_rn(v.w - __bfloat162float(hw)));
    h.x = *(uint32_t*)&h0; h.y = *(uint32_t*)&h1;
    l.x = *(uint32_t*)&l0; l.y = *(uint32_t*)&l1;
}

// hi-only pack: float4 -> 4x bf16 (8B)
__device__ __forceinline__ uint2 hi4(float4 v) {
    __nv_bfloat162 h0 = __floats2bfloat162_rn(v.x, v.y);
    __nv_bfloat162 h1 = __floats2bfloat162_rn(v.z, v.w);
    uint2 r;
    r.x = *(uint32_t*)&h0; r.y = *(uint32_t*)&h1;
    return r;
}

// ---------------------------------------------------------------------------
// LayerNorm: one block (256 thr) per row of 768
// ---------------------------------------------------------------------------
__global__ void ln_kernel(const float* __restrict__ x,
                          const float* __restrict__ gam,
                          const float* __restrict__ bet)
{
    int row = blockIdx.x;
    const float* xr = x + (size_t)row * D_SZ;
    float v[3];
    float s = 0.f, sq = 0.f;
#pragma unroll
    for (int i = 0; i < 3; i++) {
        v[i] = xr[threadIdx.x + i * 256];
        s += v[i];
        sq += v[i] * v[i];
    }
#pragma unroll
    for (int o = 16; o > 0; o >>= 1) {
        s  += __shfl_xor_sync(0xffffffffu, s, o);
        sq += __shfl_xor_sync(0xffffffffu, sq, o);
    }
    __shared__ float ss[8], ssq[8];
    int w = threadIdx.x >> 5, lane = threadIdx.x & 31;
    if (lane == 0) { ss[w] = s; ssq[w] = sq; }
    __syncthreads();
    if (w == 0) {
        s  = (lane < 8) ? ss[lane]  : 0.f;
        sq = (lane < 8) ? ssq[lane] : 0.f;
#pragma unroll
        for (int o = 4; o > 0; o >>= 1) {
            s  += __shfl_xor_sync(0xffffffffu, s, o);
            sq += __shfl_xor_sync(0xffffffffu, sq, o);
        }
        if (lane == 0) { ss[0] = s; ssq[0] = sq; }
    }
    __syncthreads();
    float mu  = ss[0] * (1.f / D_SZ);
    float var = ssq[0] * (1.f / D_SZ) - mu * mu;
    float rs  = rsqrtf(var + 1e-6f);
#pragma unroll
    for (int i = 0; i < 3; i++) {
        int c = threadIdx.x + i * 256;
        g_xn[(size_t)row * D_SZ + c] = (v[i] - mu) * rs * gam[c] + bet[c];
    }
}

// ---------------------------------------------------------------------------
// bf16-split NT GEMM: inline f32->bf16 hi/lo split at STS, ldmatrix mainloop.
// Tile 128x64x32, 256 threads (8 warps 4x2), warp tile 32x32, 2 CTAs/SM.
// NPASS=3: hi*hi + lo*hi + hi*lo  NPASS=2: drop hi*lo
// EPI 0: plain   EPI 1: softplus(acc + bias[n])   EPI 2: relu(acc)+resid
// ---------------------------------------------------------------------------
#define RSB     80                 // smem bytes per row (64 data + 16 pad)
#define TILE_A  (128 * RSB)        // 10240
#define TILE_B  (64 * RSB)         // 5120
#define STG2    (2 * TILE_A + TILE_B)            // 25600
#define STG3    (2 * TILE_A + 2 * TILE_B)        // 30720
#define GSMEM2  (2 * STG2)         // 51200
#define GSMEM3  (2 * STG3)         // 61440

template <int EPI, int NPASS>
__global__ __launch_bounds__(256, 2)
void mgemm(const float* __restrict__ A, int lda,
           const float* __restrict__ Bm, int ldb,
           float* __restrict__ C, int M, int N, int K,
           const float* __restrict__ bias,
           const float* __restrict__ resid, size_t zC)
{
    constexpr int STG = (NPASS == 3) ? STG3 : STG2;
    extern __shared__ __align__(16) char smraw[];
    uint32_t smbase = s2u(smraw);

    A += (size_t)blockIdx.z * K;
    C += (size_t)blockIdx.z * zC;

    int tid = threadIdx.x;
    int wid = tid >> 5, lane = tid & 31;
    int wm = (wid & 3) * 32;           // 4 M-positions
    int wn = (wid >> 2) * 32;          // 2 N-positions
    int grp = lane >> 2, qd = lane & 3;
    int row0 = blockIdx.y * 128, col0 = blockIdx.x * 64;

    float acc[2][4][4];
#pragma unroll
    for (int mi = 0; mi < 2; mi++)
#pragma unroll
        for (int ni = 0; ni < 4; ni++)
#pragma unroll
            for (int e = 0; e < 4; e++) acc[mi][ni][e] = 0.f;

    const int nch = (K + 31) / 32;

    // A loads: row = tid>>1 (0..127), 16 floats (4 float4)
    int arow_ld = tid >> 1;
    int acol_ld = (tid & 1) * 16;
    // B loads: row = tid>>2 (0..63), 8 floats (2 float4)
    int brow_ld = tid >> 2;
    int bcol_ld = (tid & 3) * 8;

    float4 pa[4], pb[2];

    auto loadc = [&](int c) {
        int kc = c * 32;
#pragma unroll
        for (int j = 0; j < 4; j++) {
            int col = kc + acol_ld + j * 4;
            pa[j] = (col < K)
                  ? *(const float4*)(A + (size_t)(row0 + arow_ld) * lda + col)
                  : make_float4(0.f, 0.f, 0.f, 0.f);
        }
        int n = col0 + brow_ld;
#pragma unroll
        for (int j = 0; j < 2; j++) {
            int col = kc + bcol_ld + j * 4;
            pb[j] = (col < K && n < N)
                  ? *(const float4*)(Bm + (size_t)n * ldb + col)
                  : make_float4(0.f, 0.f, 0.f, 0.f);
        }
    };

    auto storec = [&](int s) {
        uint32_t st = (uint32_t)s * STG;
#pragma unroll
        for (int j = 0; j < 4; j++) {
            uint32_t co = st + arow_ld * RSB + (acol_ld + j * 4) * 2;
            uint2 h, l;
            split4(pa[j], h, l);
            *(uint2*)(smraw + co)          = h;
            *(uint2*)(smraw + co + TILE_A) = l;
        }
#pragma unroll
        for (int j = 0; j < 2; j++) {
            uint32_t co = st + 2 * TILE_A + brow_ld * RSB + (bcol_ld + j * 4) * 2;
            if (NPASS == 3) {
                uint2 h, l;
                split4(pb[j], h, l);
                *(uint2*)(smraw + co)          = h;
                *(uint2*)(smraw + co + TILE_B) = l;
            } else {
                *(uint2*)(smraw + co) = hi4(pb[j]);
            }
        }
    };

    loadc(0);
    storec(0);
    __syncthreads();

    int arow = lane & 15;
    int asel = (lane >> 4) * 16;
    int brow = ((lane >> 4) << 3) + (lane & 7);
    int bsel = ((lane >> 3) & 1) * 16;

    for (int c = 0; c < nch; c++) {
        int s = c & 1;
        if (c + 1 < nch) loadc(c + 1);

        uint32_t stA  = smbase + (uint32_t)s * STG;
        uint32_t stAl = stA + TILE_A;
        uint32_t stB  = stA + 2 * TILE_A;
        uint32_t stBl = stB + TILE_B;

#pragma unroll
        for (int ks = 0; ks < 2; ks++) {
            int kb = ks * 32;   // byte offset of k-half
            uint32_t ahi[2][4], alo[2][4], bhi[4][2], blo[4][2];
#pragma unroll
            for (int mi = 0; mi < 2; mi++) {
                uint32_t ad = stA + (wm + mi * 16 + arow) * RSB + kb + asel;
                ldsm4(ahi[mi][0], ahi[mi][1], ahi[mi][2], ahi[mi][3], ad);
            }
#pragma unroll
            for (int nb = 0; nb < 2; nb++) {
                uint32_t bd = stB + (wn + nb * 16 + brow) * RSB + kb + bsel;
                ldsm4(bhi[2 * nb][0], bhi[2 * nb][1],
                      bhi[2 * nb + 1][0], bhi[2 * nb + 1][1], bd);
            }
            // pass 1: hi*hi
#pragma unroll
            for (int mi = 0; mi < 2; mi++)
#pragma unroll
                for (int ni = 0; ni < 4; ni++)
                    mma16(acc[mi][ni], ahi[mi], bhi[ni]);
            // pass 2: lo*hi
#pragma unroll
            for (int mi = 0; mi < 2; mi++) {
                uint32_t ad = stAl + (wm + mi * 16 + arow) * RSB + kb + asel;
                ldsm4(alo[mi][0], alo[mi][1], alo[mi][2], alo[mi][3], ad);
            }
#pragma unroll
            for (int mi = 0; mi < 2; mi++)
#pragma unroll
                for (int ni = 0; ni < 4; ni++)
                    mma16(acc[mi][ni], alo[mi], bhi[ni]);
            // pass 3: hi*lo (full precision only)
            if (NPASS == 3) {
#pragma unroll
                for (int nb = 0; nb < 2; nb++) {
                    uint32_t bd = stBl + (wn + nb * 16 + brow) * RSB + kb + bsel;
                    ldsm4(blo[2 * nb][0], blo[2 * nb][1],
                          blo[2 * nb + 1][0], blo[2 * nb + 1][1], bd);
                }
#pragma unroll
                for (int mi = 0; mi < 2; mi++)
#pragma unroll
                    for (int ni = 0; ni < 4; ni++)
                        mma16(acc[mi][ni], ahi[mi], blo[ni]);
            }
        }

        if (c + 1 < nch) storec((c + 1) & 1);
        __syncthreads();
    }

    // epilogue: registers -> gmem
#pragma unroll
    for (int mi = 0; mi < 2; mi++) {
#pragma unroll
        for (int ni = 0; ni < 4; ni++) {
            int r  = row0 + wm + mi * 16 + grp;
            int cc = col0 + wn + ni * 8 + qd * 2;
            if (cc < N) {
#pragma unroll
                for (int h = 0; h < 2; h++) {
                    int rr = r + h * 8;
                    float v0 = acc[mi][ni][h * 2 + 0];
                    float v1 = acc[mi][ni][h * 2 + 1];
                    if (EPI == 1) {
                        v0 += bias[cc];
                        v1 += bias[cc + 1];
                        v0 = (v0 > 20.f) ? v0 : log1pf(__expf(v0));
                        v1 = (v1 > 20.f) ? v1 : log1pf(__expf(v1));
                    } else if (EPI == 2) {
                        v0 = fmaxf(v0, 0.f) + resid[(size_t)rr * N + cc];
                        v1 = fmaxf(v1, 0.f) + resid[(size_t)rr * N + cc + 1];
                    }
                    float2 o; o.x = v0; o.y = v1;
                    *(float2*)(C + (size_t)rr * N + cc) = o;
                }
            }
        }
    }
}

// ---------------------------------------------------------------------------
// Reduce split-K partials for x_dbl
// ---------------------------------------------------------------------------
__global__ void xdbl_reduce_kernel()
{
    int i = blockIdx.x * 256 + threadIdx.x;
    if (i < XPART) {
        float s = g_xpart[i] + g_xpart[i + XPART]
                + g_xpart[i + 2 * XPART] + g_xpart[i + 3 * XPART];
        g_xdbl[i] = s;
    }
}

// ---------------------------------------------------------------------------
// Causal depthwise conv (width 4) + bias + SiLU; 4 outputs per thread.
// ---------------------------------------------------------------------------
__global__ void conv_silu_kernel(const float* __restrict__ Wc,
                                 const float* __restrict__ bc)
{
    int gid = blockIdx.x * blockDim.x + threadIdx.x;
    if (gid >= (M_ROWS / 4) * DI_SZ) return;
    int d   = gid % DI_SZ;
    int blk = gid / DI_SZ;
    int b   = blk / (L_SZ / 4);
    int l0  = (blk % (L_SZ / 4)) * 4;
    int bl0 = b * L_SZ + l0;

    float w0 = Wc[d * 4 + 0], w1 = Wc[d * 4 + 1];
    float w2 = Wc[d * 4 + 2], w3 = Wc[d * 4 + 3];
    float bb = bc[d];

    float x[7];
#pragma unroll
    for (int k = 0; k < 7; k++) {
        int l = l0 - 3 + k;
        x[k] = (l >= 0) ? g_xz[(size_t)(bl0 - 3 + k) * DI2_SZ + d] : 0.f;
    }
#pragma unroll
    for (int i = 0; i < 4; i++) {
        float acc = bb;
        acc = fmaf(w0, x[i],     acc);
        acc = fmaf(w1, x[i + 1], acc);
        acc = fmaf(w2, x[i + 2], acc);
        acc = fmaf(w3, x[i + 3], acc);
        g_xc[(size_t)(bl0 + i) * DI_SZ + d] = acc / (1.f + __expf(-acc));
    }
}

// ---------------------------------------------------------------------------
// Selective scan + skip + gate, 4-step batched (R9 version).
// ---------------------------------------------------------------------------
__global__ __launch_bounds__(256)
void scan_kernel(const float* __restrict__ A_log,
                 const float* __restrict__ Dpar)
{
    int gtid  = blockIdx.x * 256 + threadIdx.x;
    int chain = gtid >> 4;          // 0..6143
    int n     = gtid & 15;
    int b     = chain / DI_SZ;
    int d     = chain % DI_SZ;

    float a  = -__expf(A_log[d * N_ST + n]);
    float dp = Dpar[d];
    float h  = 0.f;
    int base = b * L_SZ;

    const float* pd = g_delta + (size_t)base * DI_SZ + d;
    const float* pu = g_xc    + (size_t)base * DI_SZ + d;
    const float* px = g_xdbl  + (size_t)base * XDBL_W + DTR_SZ + n;
    const float* pz = g_xz    + (size_t)base * DI2_SZ + DI_SZ + d;
    float*       py = g_y     + (size_t)base * DI_SZ + d;

    float dl[4], u[4], Bv[4], Cv[4], z[4];
#pragma unroll
    for (int i = 0; i < 4; i++) {
        dl[i] = pd[i * DI_SZ];
        u[i]  = pu[i * DI_SZ];
        Bv[i] = px[i * XDBL_W];
        Cv[i] = px[i * XDBL_W + N_ST];
        z[i]  = pz[i * DI2_SZ];
    }
    pd += 4 * DI_SZ; pu += 4 * DI_SZ; px += 4 * XDBL_W; pz += 4 * DI2_SZ;

    for (int blk = 0; blk < L_SZ / 4; blk++) {
        float dl2[4], u2[4], Bv2[4], Cv2[4], z2[4];
        if (blk + 1 < L_SZ / 4) {
#pragma unroll
            for (int i = 0; i < 4; i++) {
                dl2[i] = pd[i * DI_SZ];
                u2[i]  = pu[i * DI_SZ];
                Bv2[i] = px[i * XDBL_W];
                Cv2[i] = px[i * XDBL_W + N_ST];
                z2[i]  = pz[i * DI2_SZ];
            }
            pd += 4 * DI_SZ; pu += 4 * DI_SZ; px += 4 * XDBL_W; pz += 4 * DI2_SZ;
        }

        float s0, s1, s2, s3;
        {
            float dA;
            dA = __expf(dl[0] * a); h = fmaf(dA, h, dl[0] * Bv[0] * u[0]); s0 = h * Cv[0];
            dA = __expf(dl[1] * a); h = fmaf(dA, h, dl[1] * Bv[1] * u[1]); s1 = h * Cv[1];
            dA = __expf(dl[2] * a); h = fmaf(dA, h, dl[2] * Bv[2] * u[2]); s2 = h * Cv[2];
            dA = __expf(dl[3] * a); h = fmaf(dA, h, dl[3] * Bv[3] * u[3]); s3 = h * Cv[3];
        }

#pragma unroll
        for (int o = 8; o > 0; o >>= 1) {
            s0 += __shfl_xor_sync(0xffffffffu, s0, o);
            s1 += __shfl_xor_sync(0xffffffffu, s1, o);
            s2 += __shfl_xor_sync(0xffffffffu, s2, o);
            s3 += __shfl_xor_sync(0xffffffffu, s3, o);
        }

        if (n == 0) {
            float sv[4] = {s0, s1, s2, s3};
#pragma unroll
            for (int i = 0; i < 4; i++) {
                float sil = z[i] / (1.f + __expf(-z[i]));
                py[i * DI_SZ] = (sv[i] + u[i] * dp) * sil;
            }
        }
        py += 4 * DI_SZ;

#pragma unroll
        for (int i = 0; i < 4; i++) {
            dl[i] = dl2[i]; u[i] = u2[i]; Bv[i] = Bv2[i]; Cv[i] = Cv2[i]; z[i] = z2[i];
        }
    }
}

// ---------------------------------------------------------------------------
extern "C" void kernel_launch(void* const* d_in, const int* in_sizes, int n_in,
                              void* d_out, int out_size)
{
    const float* input   = (const float*)d_in[0];
    const float* ln_g    = (const float*)d_in[1];
    const float* ln_b    = (const float*)d_in[2];
    const float* W_in    = (const float*)d_in[3];
    const float* W_conv  = (const float*)d_in[4];
    const float* b_conv  = (const float*)d_in[5];
    const float* W_x     = (const float*)d_in[6];
    const float* W_dt    = (const float*)d_in[7];
    const float* b_dt    = (const float*)d_in[8];
    const float* A_log   = (const float*)d_in[9];
    const float* D_param = (const float*)d_in[10];
    const float* W_out   = (const float*)d_in[11];
    float* out = (float*)d_out;

    float *xn, *xz, *xc, *xpart, *xdbl, *delta, *y;
    cudaGetSymbolAddress((void**)&xn,    g_xn);
    cudaGetSymbolAddress((void**)&xz,    g_xz);
    cudaGetSymbolAddress((void**)&xc,    g_xc);
    cudaGetSymbolAddress((void**)&xpart, g_xpart);
    cudaGetSymbolAddress((void**)&xdbl,  g_xdbl);
    cudaGetSymbolAddress((void**)&delta, g_delta);
    cudaGetSymbolAddress((void**)&y,     g_y);

    cudaFuncSetAttribute(mgemm<0,2>, cudaFuncAttributeMaxDynamicSharedMemorySize, GSMEM2);
    cudaFuncSetAttribute(mgemm<0,3>, cudaFuncAttributeMaxDynamicSharedMemorySize, GSMEM3);
    cudaFuncSetAttribute(mgemm<1,3>, cudaFuncAttributeMaxDynamicSharedMemorySize, GSMEM3);
    cudaFuncSetAttribute(mgemm<2,2>, cudaFuncAttributeMaxDynamicSharedMemorySize, GSMEM2);

    // 1. LayerNorm
    ln_kernel<<<M_ROWS, 256>>>(input, ln_g, ln_b);

    // 2. in-proj: xz = xn @ W_in^T   (4096 x 3072 x 768) — 2-pass
    {
        dim3 g(DI2_SZ / 64, M_ROWS / 128, 1);
        mgemm<0,2><<<g, 256, GSMEM2>>>(xn, D_SZ, W_in, D_SZ, xz,
                                       M_ROWS, DI2_SZ, D_SZ, nullptr, nullptr, 0);
    }

    // 3. causal depthwise conv + SiLU -> xc
    {
        int total = (M_ROWS / 4) * DI_SZ;
        conv_silu_kernel<<<(total + 255) / 256, 256>>>(W_conv, b_conv);
    }

    // 4. x_dbl = xc @ W_x^T   (4096 x 80 x 1536) — split-K x4, 3-pass
    {
        dim3 g((XDBL_W + 63) / 64, M_ROWS / 128, KSPLIT);
        mgemm<0,3><<<g, 256, GSMEM3>>>(xc, DI_SZ, W_x, DI_SZ, xpart,
                                       M_ROWS, XDBL_W, DI_SZ / KSPLIT,
                                       nullptr, nullptr, (size_t)XPART);
        xdbl_reduce_kernel<<<(XPART + 255) / 256, 256>>>();
    }

    // 5. delta = softplus(dt @ W_dt^T + b_dt)   (4096 x 1536 x 48) — 3-pass
    {
        dim3 g(DI_SZ / 64, M_ROWS / 128, 1);
        mgemm<1,3><<<g, 256, GSMEM3>>>(xdbl, XDBL_W, W_dt, DTR_SZ, delta,
                                       M_ROWS, DI_SZ, DTR_SZ, b_dt, nullptr, 0);
    }

    // 6. selective scan + skip + gating -> y
    {
        int threads = B_SZ * DI_SZ * N_ST;   // 98304
        scan_kernel<<<threads / 256, 256>>>(A_log, D_param);
    }

    // 7. out = relu(y @ W_out^T) + input   (4096 x 768 x 1536) — 2-pass
    {
        dim3 g(D_SZ / 64, M_ROWS / 128, 1);
        mgemm<2,2><<<g, 256, GSMEM2>>>(y, DI_SZ, W_out, DI_SZ, out,
                                       M_ROWS, D_SZ, DI_SZ, nullptr, input, 0);
    }
}

// round 13
// speedup vs baseline: 1.6129x; 1.0306x over previous
#include <cuda_runtime.h>
#include <cuda_bf16.h>
#include <math.h>
#include <stdint.h>

// Problem constants
#define B_SZ   4
#define L_SZ   1024
#define D_SZ   768
#define DI_SZ  1536
#define DI2_SZ 3072
#define N_ST   16
#define DTR_SZ 48
#define XDBL_W 80           // DTR + 2*N
#define M_ROWS 4096         // B*L
#define KSPLIT 4
#define XPART  (M_ROWS * XDBL_W)

// Scratch (device globals; no allocation allowed)
__device__ float g_xn  [M_ROWS * D_SZ];
__device__ float g_xz  [M_ROWS * DI2_SZ];
__device__ float g_xc  [M_ROWS * DI_SZ];
__device__ float g_xpart[KSPLIT * XPART];
__device__ float g_xdbl[M_ROWS * XDBL_W];
__device__ float g_delta[M_ROWS * DI_SZ];
__device__ float g_y   [M_ROWS * DI_SZ];

__device__ __forceinline__ void mma16(float* d,
                                      const uint32_t* a, const uint32_t* b) {
    asm volatile(
        "mma.sync.aligned.m16n8k16.row.col.f32.bf16.bf16.f32 "
        "{%0,%1,%2,%3}, {%4,%5,%6,%7}, {%8,%9}, {%0,%1,%2,%3};"
        : "+f"(d[0]), "+f"(d[1]), "+f"(d[2]), "+f"(d[3])
        : "r"(a[0]), "r"(a[1]), "r"(a[2]), "r"(a[3]), "r"(b[0]), "r"(b[1]));
}

__device__ __forceinline__ void ldsm4(uint32_t& r0, uint32_t& r1,
                                      uint32_t& r2, uint32_t& r3, uint32_t a) {
    asm volatile("ldmatrix.sync.aligned.m8n8.x4.shared.b16 {%0,%1,%2,%3}, [%4];"
                 : "=r"(r0), "=r"(r1), "=r"(r2), "=r"(r3) : "r"(a));
}

__device__ __forceinline__ uint32_t s2u(const void* p) {
    uint32_t a;
    asm("{ .reg .u64 t; cvta.to.shared.u64 t, %1; cvt.u32.u64 %0, t; }"
        : "=r"(a) : "l"(p));
    return a;
}

// split float4 into 4x bf16 hi (8B) and 4x bf16 lo (8B)
__device__ __forceinline__ void split4(float4 v, uint2& h, uint2& l) {
    __nv_bfloat16 hx = __float2bfloat16_rn(v.x);
    __nv_bfloat16 hy = __float2bfloat16_rn(v.y);
    __nv_bfloat16 hz = __float2bfloat16_rn(v.z);
    __nv_bfloat16 hw = __float2bfloat16_rn(v.w);
    __nv_bfloat162 h0 = __halves2bfloat162(hx, hy);
    __nv_bfloat162 h1 = __halves2bfloat162(hz, hw);
    __nv_bfloat162 l0 = __halves2bfloat162(
        __float2bfloat16_rn(v.x - __bfloat162float(hx)),
        __float2bfloat16_rn(v.y - __bfloat162float(hy)));
    __nv_bfloat162 l1 = __halves2bfloat162(
        __float2bfloat16_rn(v.z - __bfloat162float(hz)),
        __float2bfloat16_rn(v.w - __bfloat162float(hw)));
    h.x = *(uint32_t*)&h0; h.y = *(uint32_t*)&h1;
    l.x = *(uint32_t*)&l0; l.y = *(uint32_t*)&l1;
}

// hi-only pack: float4 -> 4x bf16 (8B)
__device__ __forceinline__ uint2 hi4(float4 v) {
    __nv_bfloat162 h0 = __floats2bfloat162_rn(v.x, v.y);
    __nv_bfloat162 h1 = __floats2bfloat162_rn(v.z, v.w);
    uint2 r;
    r.x = *(uint32_t*)&h0; r.y = *(uint32_t*)&h1;
    return r;
}

// ---------------------------------------------------------------------------
// LayerNorm: one block (256 thr) per row of 768
// ---------------------------------------------------------------------------
__global__ void ln_kernel(const float* __restrict__ x,
                          const float* __restrict__ gam,
                          const float* __restrict__ bet)
{
    int row = blockIdx.x;
    const float* xr = x + (size_t)row * D_SZ;
    float v[3];
    float s = 0.f, sq = 0.f;
#pragma unroll
    for (int i = 0; i < 3; i++) {
        v[i] = xr[threadIdx.x + i * 256];
        s += v[i];
        sq += v[i] * v[i];
    }
#pragma unroll
    for (int o = 16; o > 0; o >>= 1) {
        s  += __shfl_xor_sync(0xffffffffu, s, o);
        sq += __shfl_xor_sync(0xffffffffu, sq, o);
    }
    __shared__ float ss[8], ssq[8];
    int w = threadIdx.x >> 5, lane = threadIdx.x & 31;
    if (lane == 0) { ss[w] = s; ssq[w] = sq; }
    __syncthreads();
    if (w == 0) {
        s  = (lane < 8) ? ss[lane]  : 0.f;
        sq = (lane < 8) ? ssq[lane] : 0.f;
#pragma unroll
        for (int o = 4; o > 0; o >>= 1) {
            s  += __shfl_xor_sync(0xffffffffu, s, o);
            sq += __shfl_xor_sync(0xffffffffu, sq, o);
        }
        if (lane == 0) { ss[0] = s; ssq[0] = sq; }
    }
    __syncthreads();
    float mu  = ss[0] * (1.f / D_SZ);
    float var = ssq[0] * (1.f / D_SZ) - mu * mu;
    float rs  = rsqrtf(var + 1e-6f);
#pragma unroll
    for (int i = 0; i < 3; i++) {
        int c = threadIdx.x + i * 256;
        g_xn[(size_t)row * D_SZ + c] = (v[i] - mu) * rs * gam[c] + bet[c];
    }
}

// ---------------------------------------------------------------------------
// bf16-split NT GEMM (R10): inline f32->bf16 hi/lo split at STS, ldmatrix
// mainloop.  Tile 128x128x32, 512 threads (16 warps 4x4), warp tile 32x32.
// NPASS=2: hi*hi + lo*hi (rel err ~5e-6 end to end)
// EPI 0: plain   EPI 1: softplus(acc + bias[n])   EPI 2: relu(acc)+resid
// ---------------------------------------------------------------------------
#define RSB    80                 // smem bytes per row (64 data + 16 pad)
#define TILEB  (128 * RSB)        // 10240
#define STAGEB (4 * TILEB)        // 40960: Ahi, Alo, Bhi, (Blo unused in 2-pass)
#define GSMEM  (2 * STAGEB)       // 81920

template <int EPI, int NPASS>
__global__ __launch_bounds__(512)
void mgemm(const float* __restrict__ A, int lda,
           const float* __restrict__ Bm, int ldb,
           float* __restrict__ C, int M, int N, int K,
           const float* __restrict__ bias,
           const float* __restrict__ resid, size_t zC)
{
    extern __shared__ __align__(16) char smraw[];
    uint32_t smbase = s2u(smraw);

    A += (size_t)blockIdx.z * K;
    C += (size_t)blockIdx.z * zC;

    int tid = threadIdx.x;
    int wid = tid >> 5, lane = tid & 31;
    int wm = (wid & 3) * 32;
    int wn = (wid >> 2) * 32;
    int grp = lane >> 2, qd = lane & 3;
    int row0 = blockIdx.y * 128, col0 = blockIdx.x * 128;

    float acc[2][4][4];
#pragma unroll
    for (int mi = 0; mi < 2; mi++)
#pragma unroll
        for (int ni = 0; ni < 4; ni++)
#pragma unroll
            for (int e = 0; e < 4; e++) acc[mi][ni][e] = 0.f;

    const int nch = (K + 31) / 32;

    int lrow = tid >> 2;           // 0..127
    int q    = tid & 3;            // float4 slot pair

    float4 pa[2], pb[2];

    auto loadc = [&](int c) {
        int kc = c * 32;
#pragma unroll
        for (int j = 0; j < 2; j++) {
            int col = kc + q * 8 + j * 4;
            bool kok = col < K;
            pa[j] = kok ? *(const float4*)(A + (size_t)(row0 + lrow) * lda + col)
                        : make_float4(0.f, 0.f, 0.f, 0.f);
            int n = col0 + lrow;
            pb[j] = (kok && n < N) ? *(const float4*)(Bm + (size_t)n * ldb + col)
                                   : make_float4(0.f, 0.f, 0.f, 0.f);
        }
    };

    auto storec = [&](int s) {
        uint32_t st = smbase + (uint32_t)s * STAGEB + lrow * RSB;
#pragma unroll
        for (int j = 0; j < 2; j++) {
            uint32_t co = (q * 8 + j * 4) * 2;
            uint2 h, l;
            split4(pa[j], h, l);
            *(uint2*)(smraw + (st - smbase) + co)             = h;
            *(uint2*)(smraw + (st - smbase) + TILEB + co)     = l;
            if (NPASS == 3) {
                split4(pb[j], h, l);
                *(uint2*)(smraw + (st - smbase) + 2 * TILEB + co) = h;
                *(uint2*)(smraw + (st - smbase) + 3 * TILEB + co) = l;
            } else {
                *(uint2*)(smraw + (st - smbase) + 2 * TILEB + co) = hi4(pb[j]);
            }
        }
    };

    loadc(0);
    storec(0);
    __syncthreads();

    int arow = lane & 15;
    int asel = (lane >> 4) * 16;
    int brow = ((lane >> 4) << 3) + (lane & 7);
    int bsel = ((lane >> 3) & 1) * 16;

    for (int c = 0; c < nch; c++) {
        int s = c & 1;
        if (c + 1 < nch) loadc(c + 1);

        uint32_t stA  = smbase + (uint32_t)s * STAGEB;
        uint32_t stAl = stA + TILEB;
        uint32_t stB  = stA + 2 * TILEB;
        uint32_t stBl = stA + 3 * TILEB;

#pragma unroll
        for (int ks = 0; ks < 2; ks++) {
            int kb = ks * 32;   // byte offset of k-half
            uint32_t ahi[2][4], alo[2][4], bhi[4][2], blo[4][2];
#pragma unroll
            for (int mi = 0; mi < 2; mi++) {
                uint32_t ad = stA + (wm + mi * 16 + arow) * RSB + kb + asel;
                ldsm4(ahi[mi][0], ahi[mi][1], ahi[mi][2], ahi[mi][3], ad);
            }
#pragma unroll
            for (int nb = 0; nb < 2; nb++) {
                uint32_t bd = stB + (wn + nb * 16 + brow) * RSB + kb + bsel;
                ldsm4(bhi[2 * nb][0], bhi[2 * nb][1],
                      bhi[2 * nb + 1][0], bhi[2 * nb + 1][1], bd);
            }
            // pass 1: hi*hi
#pragma unroll
            for (int mi = 0; mi < 2; mi++)
#pragma unroll
                for (int ni = 0; ni < 4; ni++)
                    mma16(acc[mi][ni], ahi[mi], bhi[ni]);
            // pass 2: lo*hi
#pragma unroll
            for (int mi = 0; mi < 2; mi++) {
                uint32_t ad = stAl + (wm + mi * 16 + arow) * RSB + kb + asel;
                ldsm4(alo[mi][0], alo[mi][1], alo[mi][2], alo[mi][3], ad);
            }
#pragma unroll
            for (int mi = 0; mi < 2; mi++)
#pragma unroll
                for (int ni = 0; ni < 4; ni++)
                    mma16(acc[mi][ni], alo[mi], bhi[ni]);
            // pass 3: hi*lo (only when NPASS==3)
            if (NPASS == 3) {
#pragma unroll
                for (int nb = 0; nb < 2; nb++) {
                    uint32_t bd = stBl + (wn + nb * 16 + brow) * RSB + kb + bsel;
                    ldsm4(blo[2 * nb][0], blo[2 * nb][1],
                          blo[2 * nb + 1][0], blo[2 * nb + 1][1], bd);
                }
#pragma unroll
                for (int mi = 0; mi < 2; mi++)
#pragma unroll
                    for (int ni = 0; ni < 4; ni++)
                        mma16(acc[mi][ni], ahi[mi], blo[ni]);
            }
        }

        if (c + 1 < nch) storec((c + 1) & 1);
        __syncthreads();
    }

    // epilogue: registers -> gmem
#pragma unroll
    for (int mi = 0; mi < 2; mi++) {
#pragma unroll
        for (int ni = 0; ni < 4; ni++) {
            int r  = row0 + wm + mi * 16 + grp;
            int cc = col0 + wn + ni * 8 + qd * 2;
            if (cc < N) {
#pragma unroll
                for (int h = 0; h < 2; h++) {
                    int rr = r + h * 8;
                    float v0 = acc[mi][ni][h * 2 + 0];
                    float v1 = acc[mi][ni][h * 2 + 1];
                    if (EPI == 1) {
                        v0 += bias[cc];
                        v1 += bias[cc + 1];
                        v0 = (v0 > 20.f) ? v0 : log1pf(__expf(v0));
                        v1 = (v1 > 20.f) ? v1 : log1pf(__expf(v1));
                    } else if (EPI == 2) {
                        v0 = fmaxf(v0, 0.f) + resid[(size_t)rr * N + cc];
                        v1 = fmaxf(v1, 0.f) + resid[(size_t)rr * N + cc + 1];
                    }
                    float2 o; o.x = v0; o.y = v1;
                    *(float2*)(C + (size_t)rr * N + cc) = o;
                }
            }
        }
    }
}

// ---------------------------------------------------------------------------
// Reduce split-K partials for x_dbl
// ---------------------------------------------------------------------------
__global__ void xdbl_reduce_kernel()
{
    int i = blockIdx.x * 256 + threadIdx.x;
    if (i < XPART) {
        float s = g_xpart[i] + g_xpart[i + XPART]
                + g_xpart[i + 2 * XPART] + g_xpart[i + 3 * XPART];
        g_xdbl[i] = s;
    }
}

// ---------------------------------------------------------------------------
// Causal depthwise conv (width 4) + bias + SiLU; 4 outputs per thread.
// ---------------------------------------------------------------------------
__global__ void conv_silu_kernel(const float* __restrict__ Wc,
                                 const float* __restrict__ bc)
{
    int gid = blockIdx.x * blockDim.x + threadIdx.x;
    if (gid >= (M_ROWS / 4) * DI_SZ) return;
    int d   = gid % DI_SZ;
    int blk = gid / DI_SZ;
    int b   = blk / (L_SZ / 4);
    int l0  = (blk % (L_SZ / 4)) * 4;
    int bl0 = b * L_SZ + l0;

    float w0 = Wc[d * 4 + 0], w1 = Wc[d * 4 + 1];
    float w2 = Wc[d * 4 + 2], w3 = Wc[d * 4 + 3];
    float bb = bc[d];

    float x[7];
#pragma unroll
    for (int k = 0; k < 7; k++) {
        int l = l0 - 3 + k;
        x[k] = (l >= 0) ? g_xz[(size_t)(bl0 - 3 + k) * DI2_SZ + d] : 0.f;
    }
#pragma unroll
    for (int i = 0; i < 4; i++) {
        float acc = bb;
        acc = fmaf(w0, x[i],     acc);
        acc = fmaf(w1, x[i + 1], acc);
        acc = fmaf(w2, x[i + 2], acc);
        acc = fmaf(w3, x[i + 3], acc);
        g_xc[(size_t)(bl0 + i) * DI_SZ + d] = acc / (1.f + __expf(-acc));
    }
}

// ---------------------------------------------------------------------------
// Selective scan + skip + gate, 8-step batched:
//  - operands for the next 8 steps prefetched as one 40-load block
//  - all 8 exp() are h-independent (parallel MUFU); h-chain = 8 FMAs
//  - 8 independent shfl reduction trees interleaved
// 16 lanes per (b,d) chain, 2 chains per warp.
// ---------------------------------------------------------------------------
#define SB 8
__global__ __launch_bounds__(256)
void scan_kernel(const float* __restrict__ A_log,
                 const float* __restrict__ Dpar)
{
    int gtid  = blockIdx.x * 256 + threadIdx.x;
    int chain = gtid >> 4;          // 0..6143
    int n     = gtid & 15;
    int b     = chain / DI_SZ;
    int d     = chain % DI_SZ;

    float a  = -__expf(A_log[d * N_ST + n]);
    float dp = Dpar[d];
    float h  = 0.f;
    int base = b * L_SZ;

    const float* pd = g_delta + (size_t)base * DI_SZ + d;
    const float* pu = g_xc    + (size_t)base * DI_SZ + d;
    const float* px = g_xdbl  + (size_t)base * XDBL_W + DTR_SZ + n;
    const float* pz = g_xz    + (size_t)base * DI2_SZ + DI_SZ + d;
    float*       py = g_y     + (size_t)base * DI_SZ + d;

    float dl[SB], u[SB], Bv[SB], Cv[SB], z[SB];
#pragma unroll
    for (int i = 0; i < SB; i++) {
        dl[i] = pd[i * DI_SZ];
        u[i]  = pu[i * DI_SZ];
        Bv[i] = px[i * XDBL_W];
        Cv[i] = px[i * XDBL_W + N_ST];
        z[i]  = pz[i * DI2_SZ];
    }
    pd += SB * DI_SZ; pu += SB * DI_SZ; px += SB * XDBL_W; pz += SB * DI2_SZ;

    for (int blk = 0; blk < L_SZ / SB; blk++) {
        float dl2[SB], u2[SB], Bv2[SB], Cv2[SB], z2[SB];
        if (blk + 1 < L_SZ / SB) {
#pragma unroll
            for (int i = 0; i < SB; i++) {
                dl2[i] = pd[i * DI_SZ];
                u2[i]  = pu[i * DI_SZ];
                Bv2[i] = px[i * XDBL_W];
                Cv2[i] = px[i * XDBL_W + N_ST];
                z2[i]  = pz[i * DI2_SZ];
            }
            pd += SB * DI_SZ; pu += SB * DI_SZ; px += SB * XDBL_W; pz += SB * DI2_SZ;
        }

        // parallel dA and dBu (no h dependence)
        float dA[SB], t[SB], s[SB];
#pragma unroll
        for (int i = 0; i < SB; i++) {
            dA[i] = __expf(dl[i] * a);
            t[i]  = dl[i] * Bv[i] * u[i];
        }
        // h chain: 8 dependent FMAs
#pragma unroll
        for (int i = 0; i < SB; i++) {
            h = fmaf(dA[i], h, t[i]);
            s[i] = h * Cv[i];
        }
        // 8 independent shfl reduction trees, interleaved
#pragma unroll
        for (int o = 8; o > 0; o >>= 1) {
#pragma unroll
            for (int i = 0; i < SB; i++)
                s[i] += __shfl_xor_sync(0xffffffffu, s[i], o);
        }

        if (n == 0) {
#pragma unroll
            for (int i = 0; i < SB; i++) {
                float sil = z[i] / (1.f + __expf(-z[i]));
                py[i * DI_SZ] = (s[i] + u[i] * dp) * sil;
            }
        }
        py += SB * DI_SZ;

#pragma unroll
        for (int i = 0; i < SB; i++) {
            dl[i] = dl2[i]; u[i] = u2[i]; Bv[i] = Bv2[i]; Cv[i] = Cv2[i]; z[i] = z2[i];
        }
    }
}

// ---------------------------------------------------------------------------
extern "C" void kernel_launch(void* const* d_in, const int* in_sizes, int n_in,
                              void* d_out, int out_size)
{
    const float* input   = (const float*)d_in[0];
    const float* ln_g    = (const float*)d_in[1];
    const float* ln_b    = (const float*)d_in[2];
    const float* W_in    = (const float*)d_in[3];
    const float* W_conv  = (const float*)d_in[4];
    const float* b_conv  = (const float*)d_in[5];
    const float* W_x     = (const float*)d_in[6];
    const float* W_dt    = (const float*)d_in[7];
    const float* b_dt    = (const float*)d_in[8];
    const float* A_log   = (const float*)d_in[9];
    const float* D_param = (const float*)d_in[10];
    const float* W_out   = (const float*)d_in[11];
    float* out = (float*)d_out;

    float *xn, *xz, *xc, *xpart, *xdbl, *delta, *y;
    cudaGetSymbolAddress((void**)&xn,    g_xn);
    cudaGetSymbolAddress((void**)&xz,    g_xz);
    cudaGetSymbolAddress((void**)&xc,    g_xc);
    cudaGetSymbolAddress((void**)&xpart, g_xpart);
    cudaGetSymbolAddress((void**)&xdbl,  g_xdbl);
    cudaGetSymbolAddress((void**)&delta, g_delta);
    cudaGetSymbolAddress((void**)&y,     g_y);

    cudaFuncSetAttribute(mgemm<0,2>, cudaFuncAttributeMaxDynamicSharedMemorySize, GSMEM);
    cudaFuncSetAttribute(mgemm<1,2>, cudaFuncAttributeMaxDynamicSharedMemorySize, GSMEM);
    cudaFuncSetAttribute(mgemm<2,2>, cudaFuncAttributeMaxDynamicSharedMemorySize, GSMEM);

    // 1. LayerNorm
    ln_kernel<<<M_ROWS, 256>>>(input, ln_g, ln_b);

    // 2. in-proj: xz = xn @ W_in^T   (4096 x 3072 x 768) — 2-pass
    {
        dim3 g(DI2_SZ / 128, M_ROWS / 128, 1);
        mgemm<0,2><<<g, 512, GSMEM>>>(xn, D_SZ, W_in, D_SZ, xz,
                                      M_ROWS, DI2_SZ, D_SZ, nullptr, nullptr, 0);
    }

    // 3. causal depthwise conv + SiLU -> xc
    {
        int total = (M_ROWS / 4) * DI_SZ;
        conv_silu_kernel<<<(total + 255) / 256, 256>>>(W_conv, b_conv);
    }

    // 4. x_dbl = xc @ W_x^T   (4096 x 80 x 1536) — split-K x4, 2-pass
    {
        dim3 g(1, M_ROWS / 128, KSPLIT);
        mgemm<0,2><<<g, 512, GSMEM>>>(xc, DI_SZ, W_x, DI_SZ, xpart,
                                      M_ROWS, XDBL_W, DI_SZ / KSPLIT,
                                      nullptr, nullptr, (size_t)XPART);
        xdbl_reduce_kernel<<<(XPART + 255) / 256, 256>>>();
    }

    // 5. delta = softplus(dt @ W_dt^T + b_dt)   (4096 x 1536 x 48) — 2-pass
    {
        dim3 g(DI_SZ / 128, M_ROWS / 128, 1);
        mgemm<1,2><<<g, 512, GSMEM>>>(xdbl, XDBL_W, W_dt, DTR_SZ, delta,
                                      M_ROWS, DI_SZ, DTR_SZ, b_dt, nullptr, 0);
    }

    // 6. selective scan + skip + gating -> y
    {
        int threads = B_SZ * DI_SZ * N_ST;   // 98304
        scan_kernel<<<threads / 256, 256>>>(A_log, D_param);
    }

    // 7. out = relu(y @ W_out^T) + input   (4096 x 768 x 1536) — 2-pass
    {
        dim3 g(D_SZ / 128, M_ROWS / 128, 1);
        mgemm<2,2><<<g, 512, GSMEM>>>(y, DI_SZ, W_out, DI_SZ, out,
                                      M_ROWS, D_SZ, DI_SZ, nullptr, input, 0);
    }
}

// round 14
// speedup vs baseline: 1.6323x; 1.0120x over previous
#include <cuda_runtime.h>
#include <cuda_bf16.h>
#include <math.h>
#include <stdint.h>

// Problem constants
#define B_SZ   4
#define L_SZ   1024
#define D_SZ   768
#define DI_SZ  1536
#define DI2_SZ 3072
#define N_ST   16
#define DTR_SZ 48
#define XDBL_W 80           // DTR + 2*N
#define M_ROWS 4096         // B*L
#define KSPLIT 4
#define XPART  (M_ROWS * XDBL_W)

// Scratch (device globals; no allocation allowed)
__device__ float g_xn  [M_ROWS * D_SZ];
__device__ float g_xz  [M_ROWS * DI2_SZ];
__device__ float g_xc  [M_ROWS * DI_SZ];
__device__ float g_xpart[KSPLIT * XPART];
__device__ float g_xdbl[M_ROWS * XDBL_W];
__device__ float g_delta[M_ROWS * DI_SZ];
__device__ float g_y   [M_ROWS * DI_SZ];

__device__ __forceinline__ void mma16(float* d,
                                      const uint32_t* a, const uint32_t* b) {
    asm volatile(
        "mma.sync.aligned.m16n8k16.row.col.f32.bf16.bf16.f32 "
        "{%0,%1,%2,%3}, {%4,%5,%6,%7}, {%8,%9}, {%0,%1,%2,%3};"
        : "+f"(d[0]), "+f"(d[1]), "+f"(d[2]), "+f"(d[3])
        : "r"(a[0]), "r"(a[1]), "r"(a[2]), "r"(a[3]), "r"(b[0]), "r"(b[1]));
}

__device__ __forceinline__ void ldsm4(uint32_t& r0, uint32_t& r1,
                                      uint32_t& r2, uint32_t& r3, uint32_t a) {
    asm volatile("ldmatrix.sync.aligned.m8n8.x4.shared.b16 {%0,%1,%2,%3}, [%4];"
                 : "=r"(r0), "=r"(r1), "=r"(r2), "=r"(r3) : "r"(a));
}

__device__ __forceinline__ uint32_t s2u(const void* p) {
    uint32_t a;
    asm("{ .reg .u64 t; cvta.to.shared.u64 t, %1; cvt.u32.u64 %0, t; }"
        : "=r"(a) : "l"(p));
    return a;
}

// split float4 into 4x bf16 hi (8B) and 4x bf16 lo (8B)
__device__ __forceinline__ void split4(float4 v, uint2& h, uint2& l) {
    __nv_bfloat16 hx = __float2bfloat16_rn(v.x);
    __nv_bfloat16 hy = __float2bfloat16_rn(v.y);
    __nv_bfloat16 hz = __float2bfloat16_rn(v.z);
    __nv_bfloat16 hw = __float2bfloat16_rn(v.w);
    __nv_bfloat162 h0 = __halves2bfloat162(hx, hy);
    __nv_bfloat162 h1 = __halves2bfloat162(hz, hw);
    __nv_bfloat162 l0 = __halves2bfloat162(
        __float2bfloat16_rn(v.x - __bfloat162float(hx)),
        __float2bfloat16_rn(v.y - __bfloat162float(hy)));
    __nv_bfloat162 l1 = __halves2bfloat162(
        __float2bfloat16_rn(v.z - __bfloat162float(hz)),
        __float2bfloat16_rn(v.w - __bfloat162float(hw)));
    h.x = *(uint32_t*)&h0; h.y = *(uint32_t*)&h1;
    l.x = *(uint32_t*)&l0; l.y = *(uint32_t*)&l1;
}

// hi-only pack: float4 -> 4x bf16 (8B)
__device__ __forceinline__ uint2 hi4(float4 v) {
    __nv_bfloat162 h0 = __floats2bfloat162_rn(v.x, v.y);
    __nv_bfloat162 h1 = __floats2bfloat162_rn(v.z, v.w);
    uint2 r;
    r.x = *(uint32_t*)&h0; r.y = *(uint32_t*)&h1;
    return r;
}

// ---------------------------------------------------------------------------
// LayerNorm: one block (256 thr) per row of 768
// ---------------------------------------------------------------------------
__global__ void ln_kernel(const float* __restrict__ x,
                          const float* __restrict__ gam,
                          const float* __restrict__ bet)
{
    int row = blockIdx.x;
    const float* xr = x + (size_t)row * D_SZ;
    float v[3];
    float s = 0.f, sq = 0.f;
#pragma unroll
    for (int i = 0; i < 3; i++) {
        v[i] = xr[threadIdx.x + i * 256];
        s += v[i];
        sq += v[i] * v[i];
    }
#pragma unroll
    for (int o = 16; o > 0; o >>= 1) {
        s  += __shfl_xor_sync(0xffffffffu, s, o);
        sq += __shfl_xor_sync(0xffffffffu, sq, o);
    }
    __shared__ float ss[8], ssq[8];
    int w = threadIdx.x >> 5, lane = threadIdx.x & 31;
    if (lane == 0) { ss[w] = s; ssq[w] = sq; }
    __syncthreads();
    if (w == 0) {
        s  = (lane < 8) ? ss[lane]  : 0.f;
        sq = (lane < 8) ? ssq[lane] : 0.f;
#pragma unroll
        for (int o = 4; o > 0; o >>= 1) {
            s  += __shfl_xor_sync(0xffffffffu, s, o);
            sq += __shfl_xor_sync(0xffffffffu, sq, o);
        }
        if (lane == 0) { ss[0] = s; ssq[0] = sq; }
    }
    __syncthreads();
    float mu  = ss[0] * (1.f / D_SZ);
    float var = ssq[0] * (1.f / D_SZ) - mu * mu;
    float rs  = rsqrtf(var + 1e-6f);
#pragma unroll
    for (int i = 0; i < 3; i++) {
        int c = threadIdx.x + i * 256;
        g_xn[(size_t)row * D_SZ + c] = (v[i] - mu) * rs * gam[c] + bet[c];
    }
}

// ---------------------------------------------------------------------------
// bf16-split NT GEMM (R10): inline f32->bf16 hi/lo split at STS, ldmatrix
// mainloop.  Tile 128x128x32, 512 threads (16 warps 4x4), warp tile 32x32.
// NPASS=2: hi*hi + lo*hi (rel err ~5e-6 end to end)
// EPI 0: plain   EPI 1: softplus(acc + bias[n])   EPI 2: relu(acc)+resid
// ---------------------------------------------------------------------------
#define RSB    80                 // smem bytes per row (64 data + 16 pad)
#define TILEB  (128 * RSB)        // 10240
#define STAGEB (4 * TILEB)        // 40960: Ahi, Alo, Bhi, (Blo unused in 2-pass)
#define GSMEM  (2 * STAGEB)       // 81920

template <int EPI, int NPASS>
__global__ __launch_bounds__(512)
void mgemm(const float* __restrict__ A, int lda,
           const float* __restrict__ Bm, int ldb,
           float* __restrict__ C, int M, int N, int K,
           const float* __restrict__ bias,
           const float* __restrict__ resid, size_t zC)
{
    extern __shared__ __align__(16) char smraw[];
    uint32_t smbase = s2u(smraw);

    A += (size_t)blockIdx.z * K;
    C += (size_t)blockIdx.z * zC;

    int tid = threadIdx.x;
    int wid = tid >> 5, lane = tid & 31;
    int wm = (wid & 3) * 32;
    int wn = (wid >> 2) * 32;
    int grp = lane >> 2, qd = lane & 3;
    int row0 = blockIdx.y * 128, col0 = blockIdx.x * 128;

    float acc[2][4][4];
#pragma unroll
    for (int mi = 0; mi < 2; mi++)
#pragma unroll
        for (int ni = 0; ni < 4; ni++)
#pragma unroll
            for (int e = 0; e < 4; e++) acc[mi][ni][e] = 0.f;

    const int nch = (K + 31) / 32;

    int lrow = tid >> 2;           // 0..127
    int q    = tid & 3;            // float4 slot pair

    float4 pa[2], pb[2];

    auto loadc = [&](int c) {
        int kc = c * 32;
#pragma unroll
        for (int j = 0; j < 2; j++) {
            int col = kc + q * 8 + j * 4;
            bool kok = col < K;
            pa[j] = kok ? *(const float4*)(A + (size_t)(row0 + lrow) * lda + col)
                        : make_float4(0.f, 0.f, 0.f, 0.f);
            int n = col0 + lrow;
            pb[j] = (kok && n < N) ? *(const float4*)(Bm + (size_t)n * ldb + col)
                                   : make_float4(0.f, 0.f, 0.f, 0.f);
        }
    };

    auto storec = [&](int s) {
        uint32_t st = smbase + (uint32_t)s * STAGEB + lrow * RSB;
#pragma unroll
        for (int j = 0; j < 2; j++) {
            uint32_t co = (q * 8 + j * 4) * 2;
            uint2 h, l;
            split4(pa[j], h, l);
            *(uint2*)(smraw + (st - smbase) + co)             = h;
            *(uint2*)(smraw + (st - smbase) + TILEB + co)     = l;
            if (NPASS == 3) {
                split4(pb[j], h, l);
                *(uint2*)(smraw + (st - smbase) + 2 * TILEB + co) = h;
                *(uint2*)(smraw + (st - smbase) + 3 * TILEB + co) = l;
            } else {
                *(uint2*)(smraw + (st - smbase) + 2 * TILEB + co) = hi4(pb[j]);
            }
        }
    };

    loadc(0);
    storec(0);
    __syncthreads();

    int arow = lane & 15;
    int asel = (lane >> 4) * 16;
    int brow = ((lane >> 4) << 3) + (lane & 7);
    int bsel = ((lane >> 3) & 1) * 16;

    for (int c = 0; c < nch; c++) {
        int s = c & 1;
        if (c + 1 < nch) loadc(c + 1);

        uint32_t stA  = smbase + (uint32_t)s * STAGEB;
        uint32_t stAl = stA + TILEB;
        uint32_t stB  = stA + 2 * TILEB;
        uint32_t stBl = stA + 3 * TILEB;

#pragma unroll
        for (int ks = 0; ks < 2; ks++) {
            int kb = ks * 32;   // byte offset of k-half
            uint32_t ahi[2][4], alo[2][4], bhi[4][2], blo[4][2];
#pragma unroll
            for (int mi = 0; mi < 2; mi++) {
                uint32_t ad = stA + (wm + mi * 16 + arow) * RSB + kb + asel;
                ldsm4(ahi[mi][0], ahi[mi][1], ahi[mi][2], ahi[mi][3], ad);
            }
#pragma unroll
            for (int nb = 0; nb < 2; nb++) {
                uint32_t bd = stB + (wn + nb * 16 + brow) * RSB + kb + bsel;
                ldsm4(bhi[2 * nb][0], bhi[2 * nb][1],
                      bhi[2 * nb + 1][0], bhi[2 * nb + 1][1], bd);
            }
            // pass 1: hi*hi
#pragma unroll
            for (int mi = 0; mi < 2; mi++)
#pragma unroll
                for (int ni = 0; ni < 4; ni++)
                    mma16(acc[mi][ni], ahi[mi], bhi[ni]);
            // pass 2: lo*hi
#pragma unroll
            for (int mi = 0; mi < 2; mi++) {
                uint32_t ad = stAl + (wm + mi * 16 + arow) * RSB + kb + asel;
                ldsm4(alo[mi][0], alo[mi][1], alo[mi][2], alo[mi][3], ad);
            }
#pragma unroll
            for (int mi = 0; mi < 2; mi++)
#pragma unroll
                for (int ni = 0; ni < 4; ni++)
                    mma16(acc[mi][ni], alo[mi], bhi[ni]);
            // pass 3: hi*lo (only when NPASS==3)
            if (NPASS == 3) {
#pragma unroll
                for (int nb = 0; nb < 2; nb++) {
                    uint32_t bd = stBl + (wn + nb * 16 + brow) * RSB + kb + bsel;
                    ldsm4(blo[2 * nb][0], blo[2 * nb][1],
                          blo[2 * nb + 1][0], blo[2 * nb + 1][1], bd);
                }
#pragma unroll
                for (int mi = 0; mi < 2; mi++)
#pragma unroll
                    for (int ni = 0; ni < 4; ni++)
                        mma16(acc[mi][ni], ahi[mi], blo[ni]);
            }
        }

        if (c + 1 < nch) storec((c + 1) & 1);
        __syncthreads();
    }

    // epilogue: registers -> gmem
#pragma unroll
    for (int mi = 0; mi < 2; mi++) {
#pragma unroll
        for (int ni = 0; ni < 4; ni++) {
            int r  = row0 + wm + mi * 16 + grp;
            int cc = col0 + wn + ni * 8 + qd * 2;
            if (cc < N) {
#pragma unroll
                for (int h = 0; h < 2; h++) {
                    int rr = r + h * 8;
                    float v0 = acc[mi][ni][h * 2 + 0];
                    float v1 = acc[mi][ni][h * 2 + 1];
                    if (EPI == 1) {
                        v0 += bias[cc];
                        v1 += bias[cc + 1];
                        v0 = (v0 > 20.f) ? v0 : log1pf(__expf(v0));
                        v1 = (v1 > 20.f) ? v1 : log1pf(__expf(v1));
                    } else if (EPI == 2) {
                        v0 = fmaxf(v0, 0.f) + resid[(size_t)rr * N + cc];
                        v1 = fmaxf(v1, 0.f) + resid[(size_t)rr * N + cc + 1];
                    }
                    float2 o; o.x = v0; o.y = v1;
                    *(float2*)(C + (size_t)rr * N + cc) = o;
                }
            }
        }
    }
}

// ---------------------------------------------------------------------------
// Reduce split-K partials for x_dbl
// ---------------------------------------------------------------------------
__global__ void xdbl_reduce_kernel()
{
    int i = blockIdx.x * 256 + threadIdx.x;
    if (i < XPART) {
        float s = g_xpart[i] + g_xpart[i + XPART]
                + g_xpart[i + 2 * XPART] + g_xpart[i + 3 * XPART];
        g_xdbl[i] = s;
    }
}

// ---------------------------------------------------------------------------
// Causal depthwise conv (width 4) + bias + SiLU; 4 outputs per thread.
// ---------------------------------------------------------------------------
__global__ void conv_silu_kernel(const float* __restrict__ Wc,
                                 const float* __restrict__ bc)
{
    int gid = blockIdx.x * blockDim.x + threadIdx.x;
    if (gid >= (M_ROWS / 4) * DI_SZ) return;
    int d   = gid % DI_SZ;
    int blk = gid / DI_SZ;
    int b   = blk / (L_SZ / 4);
    int l0  = (blk % (L_SZ / 4)) * 4;
    int bl0 = b * L_SZ + l0;

    float w0 = Wc[d * 4 + 0], w1 = Wc[d * 4 + 1];
    float w2 = Wc[d * 4 + 2], w3 = Wc[d * 4 + 3];
    float bb = bc[d];

    float x[7];
#pragma unroll
    for (int k = 0; k < 7; k++) {
        int l = l0 - 3 + k;
        x[k] = (l >= 0) ? g_xz[(size_t)(bl0 - 3 + k) * DI2_SZ + d] : 0.f;
    }
#pragma unroll
    for (int i = 0; i < 4; i++) {
        float acc = bb;
        acc = fmaf(w0, x[i],     acc);
        acc = fmaf(w1, x[i + 1], acc);
        acc = fmaf(w2, x[i + 2], acc);
        acc = fmaf(w3, x[i + 3], acc);
        g_xc[(size_t)(bl0 + i) * DI_SZ + d] = acc / (1.f + __expf(-acc));
    }
}

// ---------------------------------------------------------------------------
// Selective scan + skip + gate, 4-step batched (R9/R10 version).
// ---------------------------------------------------------------------------
__global__ __launch_bounds__(256)
void scan_kernel(const float* __restrict__ A_log,
                 const float* __restrict__ Dpar)
{
    int gtid  = blockIdx.x * 256 + threadIdx.x;
    int chain = gtid >> 4;          // 0..6143
    int n     = gtid & 15;
    int b     = chain / DI_SZ;
    int d     = chain % DI_SZ;

    float a  = -__expf(A_log[d * N_ST + n]);
    float dp = Dpar[d];
    float h  = 0.f;
    int base = b * L_SZ;

    const float* pd = g_delta + (size_t)base * DI_SZ + d;
    const float* pu = g_xc    + (size_t)base * DI_SZ + d;
    const float* px = g_xdbl  + (size_t)base * XDBL_W + DTR_SZ + n;
    const float* pz = g_xz    + (size_t)base * DI2_SZ + DI_SZ + d;
    float*       py = g_y     + (size_t)base * DI_SZ + d;

    float dl[4], u[4], Bv[4], Cv[4], z[4];
#pragma unroll
    for (int i = 0; i < 4; i++) {
        dl[i] = pd[i * DI_SZ];
        u[i]  = pu[i * DI_SZ];
        Bv[i] = px[i * XDBL_W];
        Cv[i] = px[i * XDBL_W + N_ST];
        z[i]  = pz[i * DI2_SZ];
    }
    pd += 4 * DI_SZ; pu += 4 * DI_SZ; px += 4 * XDBL_W; pz += 4 * DI2_SZ;

    for (int blk = 0; blk < L_SZ / 4; blk++) {
        float dl2[4], u2[4], Bv2[4], Cv2[4], z2[4];
        if (blk + 1 < L_SZ / 4) {
#pragma unroll
            for (int i = 0; i < 4; i++) {
                dl2[i] = pd[i * DI_SZ];
                u2[i]  = pu[i * DI_SZ];
                Bv2[i] = px[i * XDBL_W];
                Cv2[i] = px[i * XDBL_W + N_ST];
                z2[i]  = pz[i * DI2_SZ];
            }
            pd += 4 * DI_SZ; pu += 4 * DI_SZ; px += 4 * XDBL_W; pz += 4 * DI2_SZ;
        }

        float s0, s1, s2, s3;
        {
            float dA;
            dA = __expf(dl[0] * a); h = fmaf(dA, h, dl[0] * Bv[0] * u[0]); s0 = h * Cv[0];
            dA = __expf(dl[1] * a); h = fmaf(dA, h, dl[1] * Bv[1] * u[1]); s1 = h * Cv[1];
            dA = __expf(dl[2] * a); h = fmaf(dA, h, dl[2] * Bv[2] * u[2]); s2 = h * Cv[2];
            dA = __expf(dl[3] * a); h = fmaf(dA, h, dl[3] * Bv[3] * u[3]); s3 = h * Cv[3];
        }

#pragma unroll
        for (int o = 8; o > 0; o >>= 1) {
            s0 += __shfl_xor_sync(0xffffffffu, s0, o);
            s1 += __shfl_xor_sync(0xffffffffu, s1, o);
            s2 += __shfl_xor_sync(0xffffffffu, s2, o);
            s3 += __shfl_xor_sync(0xffffffffu, s3, o);
        }

        if (n == 0) {
            float sv[4] = {s0, s1, s2, s3};
#pragma unroll
            for (int i = 0; i < 4; i++) {
                float sil = z[i] / (1.f + __expf(-z[i]));
                py[i * DI_SZ] = (sv[i] + u[i] * dp) * sil;
            }
        }
        py += 4 * DI_SZ;

#pragma unroll
        for (int i = 0; i < 4; i++) {
            dl[i] = dl2[i]; u[i] = u2[i]; Bv[i] = Bv2[i]; Cv[i] = Cv2[i]; z[i] = z2[i];
        }
    }
}

// ---------------------------------------------------------------------------
extern "C" void kernel_launch(void* const* d_in, const int* in_sizes, int n_in,
                              void* d_out, int out_size)
{
    const float* input   = (const float*)d_in[0];
    const float* ln_g    = (const float*)d_in[1];
    const float* ln_b    = (const float*)d_in[2];
    const float* W_in    = (const float*)d_in[3];
    const float* W_conv  = (const float*)d_in[4];
    const float* b_conv  = (const float*)d_in[5];
    const float* W_x     = (const float*)d_in[6];
    const float* W_dt    = (const float*)d_in[7];
    const float* b_dt    = (const float*)d_in[8];
    const float* A_log   = (const float*)d_in[9];
    const float* D_param = (const float*)d_in[10];
    const float* W_out   = (const float*)d_in[11];
    float* out = (float*)d_out;

    float *xn, *xz, *xc, *xpart, *xdbl, *delta, *y;
    cudaGetSymbolAddress((void**)&xn,    g_xn);
    cudaGetSymbolAddress((void**)&xz,    g_xz);
    cudaGetSymbolAddress((void**)&xc,    g_xc);
    cudaGetSymbolAddress((void**)&xpart, g_xpart);
    cudaGetSymbolAddress((void**)&xdbl,  g_xdbl);
    cudaGetSymbolAddress((void**)&delta, g_delta);
    cudaGetSymbolAddress((void**)&y,     g_y);

    cudaFuncSetAttribute(mgemm<0,2>, cudaFuncAttributeMaxDynamicSharedMemorySize, GSMEM);
    cudaFuncSetAttribute(mgemm<1,2>, cudaFuncAttributeMaxDynamicSharedMemorySize, GSMEM);
    cudaFuncSetAttribute(mgemm<2,2>, cudaFuncAttributeMaxDynamicSharedMemorySize, GSMEM);

    // 1. LayerNorm
    ln_kernel<<<M_ROWS, 256>>>(input, ln_g, ln_b);

    // 2. in-proj: xz = xn @ W_in^T   (4096 x 3072 x 768) — 2-pass
    {
        dim3 g(DI2_SZ / 128, M_ROWS / 128, 1);
        mgemm<0,2><<<g, 512, GSMEM>>>(xn, D_SZ, W_in, D_SZ, xz,
                                      M_ROWS, DI2_SZ, D_SZ, nullptr, nullptr, 0);
    }

    // 3. causal depthwise conv + SiLU -> xc
    {
        int total = (M_ROWS / 4) * DI_SZ;
        conv_silu_kernel<<<(total + 255) / 256, 256>>>(W_conv, b_conv);
    }

    // 4. x_dbl = xc @ W_x^T   (4096 x 80 x 1536) — split-K x4, 2-pass
    {
        dim3 g(1, M_ROWS / 128, KSPLIT);
        mgemm<0,2><<<g, 512, GSMEM>>>(xc, DI_SZ, W_x, DI_SZ, xpart,
                                      M_ROWS, XDBL_W, DI_SZ / KSPLIT,
                                      nullptr, nullptr, (size_t)XPART);
        xdbl_reduce_kernel<<<(XPART + 255) / 256, 256>>>();
    }

    // 5. delta = softplus(dt @ W_dt^T + b_dt)   (4096 x 1536 x 48) — 2-pass
    {
        dim3 g(DI_SZ / 128, M_ROWS / 128, 1);
        mgemm<1,2><<<g, 512, GSMEM>>>(xdbl, XDBL_W, W_dt, DTR_SZ, delta,
                                      M_ROWS, DI_SZ, DTR_SZ, b_dt, nullptr, 0);
    }

    // 6. selective scan + skip + gating -> y
    {
        int threads = B_SZ * DI_SZ * N_ST;   // 98304
        scan_kernel<<<threads / 256, 256>>>(A_log, D_param);
    }

    // 7. out = relu(y @ W_out^T) + input   (4096 x 768 x 1536) — 2-pass
    {
        dim3 g(D_SZ / 128, M_ROWS / 128, 1);
        mgemm<2,2><<<g, 512, GSMEM>>>(y, DI_SZ, W_out, DI_SZ, out,
                                      M_ROWS, D_SZ, DI_SZ, nullptr, input, 0);
    }
}

// round 16
// speedup vs baseline: 1.7181x; 1.0526x over previous
#include <cuda_runtime.h>
#include <cuda_bf16.h>
#include <math.h>
#include <stdint.h>

// Problem constants
#define B_SZ   4
#define L_SZ   1024
#define D_SZ   768
#define DI_SZ  1536
#define DI2_SZ 3072
#define N_ST   16
#define DTR_SZ 48
#define XDBL_W 80           // DTR + 2*N
#define M_ROWS 4096         // B*L
#define KSPLIT 4
#define XPART  (M_ROWS * XDBL_W)
#define OSPLIT 3
#define OPART  (M_ROWS * D_SZ)

// Scratch (device globals; no allocation allowed)
__device__ float g_xn  [M_ROWS * D_SZ];
__device__ float g_xz  [M_ROWS * DI2_SZ];
__device__ float g_xc  [M_ROWS * DI_SZ];
__device__ float g_xpart[KSPLIT * XPART];
__device__ float g_xdbl[M_ROWS * XDBL_W];
__device__ float g_delta[M_ROWS * DI_SZ];
__device__ float g_y   [M_ROWS * DI_SZ];
__device__ float g_opart[OSPLIT * OPART];

__device__ __forceinline__ void mma16(float* d,
                                      const uint32_t* a, const uint32_t* b) {
    asm volatile(
        "mma.sync.aligned.m16n8k16.row.col.f32.bf16.bf16.f32 "
        "{%0,%1,%2,%3}, {%4,%5,%6,%7}, {%8,%9}, {%0,%1,%2,%3};"
        : "+f"(d[0]), "+f"(d[1]), "+f"(d[2]), "+f"(d[3])
        : "r"(a[0]), "r"(a[1]), "r"(a[2]), "r"(a[3]), "r"(b[0]), "r"(b[1]));
}

__device__ __forceinline__ void ldsm4(uint32_t& r0, uint32_t& r1,
                                      uint32_t& r2, uint32_t& r3, uint32_t a) {
    asm volatile("ldmatrix.sync.aligned.m8n8.x4.shared.b16 {%0,%1,%2,%3}, [%4];"
                 : "=r"(r0), "=r"(r1), "=r"(r2), "=r"(r3) : "r"(a));
}

__device__ __forceinline__ uint32_t s2u(const void* p) {
    uint32_t a;
    asm("{ .reg .u64 t; cvta.to.shared.u64 t, %1; cvt.u32.u64 %0, t; }"
        : "=r"(a) : "l"(p));
    return a;
}

// split float4 into 4x bf16 hi (8B) and 4x bf16 lo (8B)
__device__ __forceinline__ void split4(float4 v, uint2& h, uint2& l) {
    __nv_bfloat16 hx = __float2bfloat16_rn(v.x);
    __nv_bfloat16 hy = __float2bfloat16_rn(v.y);
    __nv_bfloat16 hz = __float2bfloat16_rn(v.z);
    __nv_bfloat16 hw = __float2bfloat16_rn(v.w);
    __nv_bfloat162 h0 = __halves2bfloat162(hx, hy);
    __nv_bfloat162 h1 = __halves2bfloat162(hz, hw);
    __nv_bfloat162 l0 = __halves2bfloat162(
        __float2bfloat16_rn(v.x - __bfloat162float(hx)),
        __float2bfloat16_rn(v.y - __bfloat162float(hy)));
    __nv_bfloat162 l1 = __halves2bfloat162(
        __float2bfloat16_rn(v.z - __bfloat162float(hz)),
        __float2bfloat16_rn(v.w - __bfloat162float(hw)));
    h.x = *(uint32_t*)&h0; h.y = *(uint32_t*)&h1;
    l.x = *(uint32_t*)&l0; l.y = *(uint32_t*)&l1;
}

// hi-only pack: float4 -> 4x bf16 (8B)
__device__ __forceinline__ uint2 hi4(float4 v) {
    __nv_bfloat162 h0 = __floats2bfloat162_rn(v.x, v.y);
    __nv_bfloat162 h1 = __floats2bfloat162_rn(v.z, v.w);
    uint2 r;
    r.x = *(uint32_t*)&h0; r.y = *(uint32_t*)&h1;
    return r;
}

// ---------------------------------------------------------------------------
// LayerNorm: one block (256 thr) per row of 768
// ---------------------------------------------------------------------------
__global__ void ln_kernel(const float* __restrict__ x,
                          const float* __restrict__ gam,
                          const float* __restrict__ bet)
{
    int row = blockIdx.x;
    const float* xr = x + (size_t)row * D_SZ;
    float v[3];
    float s = 0.f, sq = 0.f;
#pragma unroll
    for (int i = 0; i < 3; i++) {
        v[i] = xr[threadIdx.x + i * 256];
        s += v[i];
        sq += v[i] * v[i];
    }
#pragma unroll
    for (int o = 16; o > 0; o >>= 1) {
        s  += __shfl_xor_sync(0xffffffffu, s, o);
        sq += __shfl_xor_sync(0xffffffffu, sq, o);
    }
    __shared__ float ss[8], ssq[8];
    int w = threadIdx.x >> 5, lane = threadIdx.x & 31;
    if (lane == 0) { ss[w] = s; ssq[w] = sq; }
    __syncthreads();
    if (w == 0) {
        s  = (lane < 8) ? ss[lane]  : 0.f;
        sq = (lane < 8) ? ssq[lane] : 0.f;
#pragma unroll
        for (int o = 4; o > 0; o >>= 1) {
            s  += __shfl_xor_sync(0xffffffffu, s, o);
            sq += __shfl_xor_sync(0xffffffffu, sq, o);
        }
        if (lane == 0) { ss[0] = s; ssq[0] = sq; }
    }
    __syncthreads();
    float mu  = ss[0] * (1.f / D_SZ);
    float var = ssq[0] * (1.f / D_SZ) - mu * mu;
    float rs  = rsqrtf(var + 1e-6f);
#pragma unroll
    for (int i = 0; i < 3; i++) {
        int c = threadIdx.x + i * 256;
        g_xn[(size_t)row * D_SZ + c] = (v[i] - mu) * rs * gam[c] + bet[c];
    }
}

// ---------------------------------------------------------------------------
// bf16-split NT GEMM: inline f32->bf16 hi/lo split at STS, ldmatrix mainloop.
// Tile 128x128x32, 512 threads (16 warps 4x4), warp tile 32x32.
// Split-K via gridDim.z: BOTH A and B advance by z*K columns (bug fixed).
// NPASS=2: hi*hi + lo*hi
// EPI 0: plain   EPI 1: softplus(acc + bias[n])   EPI 2: relu(acc)+resid
// ---------------------------------------------------------------------------
#define RSB    80                 // smem bytes per row (64 data + 16 pad)
#define TILEB  (128 * RSB)        // 10240
#define STAGEB (4 * TILEB)        // 40960
#define GSMEM  (2 * STAGEB)       // 81920

template <int EPI, int NPASS>
__global__ __launch_bounds__(512)
void mgemm(const float* __restrict__ A, int lda,
           const float* __restrict__ Bm, int ldb,
           float* __restrict__ C, int M, int N, int K,
           const float* __restrict__ bias,
           const float* __restrict__ resid, size_t zC)
{
    extern __shared__ __align__(16) char smraw[];
    uint32_t smbase = s2u(smraw);

    A  += (size_t)blockIdx.z * K;      // split-K slice of A
    Bm += (size_t)blockIdx.z * K;      // split-K slice of B (THE FIX)
    C  += (size_t)blockIdx.z * zC;

    int tid = threadIdx.x;
    int wid = tid >> 5, lane = tid & 31;
    int wm = (wid & 3) * 32;
    int wn = (wid >> 2) * 32;
    int grp = lane >> 2, qd = lane & 3;
    int row0 = blockIdx.y * 128, col0 = blockIdx.x * 128;

    float acc[2][4][4];
#pragma unroll
    for (int mi = 0; mi < 2; mi++)
#pragma unroll
        for (int ni = 0; ni < 4; ni++)
#pragma unroll
            for (int e = 0; e < 4; e++) acc[mi][ni][e] = 0.f;

    const int nch = (K + 31) / 32;

    int lrow = tid >> 2;           // 0..127
    int q    = tid & 3;            // float4 slot pair

    float4 pa[2], pb[2];

    auto loadc = [&](int c) {
        int kc = c * 32;
#pragma unroll
        for (int j = 0; j < 2; j++) {
            int col = kc + q * 8 + j * 4;
            bool kok = col < K;
            pa[j] = kok ? *(const float4*)(A + (size_t)(row0 + lrow) * lda + col)
                        : make_float4(0.f, 0.f, 0.f, 0.f);
            int n = col0 + lrow;
            pb[j] = (kok && n < N) ? *(const float4*)(Bm + (size_t)n * ldb + col)
                                   : make_float4(0.f, 0.f, 0.f, 0.f);
        }
    };

    auto storec = [&](int s) {
        uint32_t st = smbase + (uint32_t)s * STAGEB + lrow * RSB;
#pragma unroll
        for (int j = 0; j < 2; j++) {
            uint32_t co = (q * 8 + j * 4) * 2;
            uint2 h, l;
            split4(pa[j], h, l);
            *(uint2*)(smraw + (st - smbase) + co)             = h;
            *(uint2*)(smraw + (st - smbase) + TILEB + co)     = l;
            if (NPASS == 3) {
                split4(pb[j], h, l);
                *(uint2*)(smraw + (st - smbase) + 2 * TILEB + co) = h;
                *(uint2*)(smraw + (st - smbase) + 3 * TILEB + co) = l;
            } else {
                *(uint2*)(smraw + (st - smbase) + 2 * TILEB + co) = hi4(pb[j]);
            }
        }
    };

    loadc(0);
    storec(0);
    __syncthreads();

    int arow = lane & 15;
    int asel = (lane >> 4) * 16;
    int brow = ((lane >> 4) << 3) + (lane & 7);
    int bsel = ((lane >> 3) & 1) * 16;

    for (int c = 0; c < nch; c++) {
        int s = c & 1;
        if (c + 1 < nch) loadc(c + 1);

        uint32_t stA  = smbase + (uint32_t)s * STAGEB;
        uint32_t stAl = stA + TILEB;
        uint32_t stB  = stA + 2 * TILEB;
        uint32_t stBl = stA + 3 * TILEB;

#pragma unroll
        for (int ks = 0; ks < 2; ks++) {
            int kb = ks * 32;   // byte offset of k-half
            uint32_t ahi[2][4], alo[2][4], bhi[4][2], blo[4][2];
#pragma unroll
            for (int mi = 0; mi < 2; mi++) {
                uint32_t ad = stA + (wm + mi * 16 + arow) * RSB + kb + asel;
                ldsm4(ahi[mi][0], ahi[mi][1], ahi[mi][2], ahi[mi][3], ad);
            }
#pragma unroll
            for (int nb = 0; nb < 2; nb++) {
                uint32_t bd = stB + (wn + nb * 16 + brow) * RSB + kb + bsel;
                ldsm4(bhi[2 * nb][0], bhi[2 * nb][1],
                      bhi[2 * nb + 1][0], bhi[2 * nb + 1][1], bd);
            }
            // pass 1: hi*hi
#pragma unroll
            for (int mi = 0; mi < 2; mi++)
#pragma unroll
                for (int ni = 0; ni < 4; ni++)
                    mma16(acc[mi][ni], ahi[mi], bhi[ni]);
            // pass 2: lo*hi
#pragma unroll
            for (int mi = 0; mi < 2; mi++) {
                uint32_t ad = stAl + (wm + mi * 16 + arow) * RSB + kb + asel;
                ldsm4(alo[mi][0], alo[mi][1], alo[mi][2], alo[mi][3], ad);
            }
#pragma unroll
            for (int mi = 0; mi < 2; mi++)
#pragma unroll
                for (int ni = 0; ni < 4; ni++)
                    mma16(acc[mi][ni], alo[mi], bhi[ni]);
            // pass 3: hi*lo (only when NPASS==3)
            if (NPASS == 3) {
#pragma unroll
                for (int nb = 0; nb < 2; nb++) {
                    uint32_t bd = stBl + (wn + nb * 16 + brow) * RSB + kb + bsel;
                    ldsm4(blo[2 * nb][0], blo[2 * nb][1],
                          blo[2 * nb + 1][0], blo[2 * nb + 1][1], bd);
                }
#pragma unroll
                for (int mi = 0; mi < 2; mi++)
#pragma unroll
                    for (int ni = 0; ni < 4; ni++)
                        mma16(acc[mi][ni], ahi[mi], blo[ni]);
            }
        }

        if (c + 1 < nch) storec((c + 1) & 1);
        __syncthreads();
    }

    // epilogue: registers -> gmem
#pragma unroll
    for (int mi = 0; mi < 2; mi++) {
#pragma unroll
        for (int ni = 0; ni < 4; ni++) {
            int r  = row0 + wm + mi * 16 + grp;
            int cc = col0 + wn + ni * 8 + qd * 2;
            if (cc < N) {
#pragma unroll
                for (int h = 0; h < 2; h++) {
                    int rr = r + h * 8;
                    float v0 = acc[mi][ni][h * 2 + 0];
                    float v1 = acc[mi][ni][h * 2 + 1];
                    if (EPI == 1) {
                        v0 += bias[cc];
                        v1 += bias[cc + 1];
                        v0 = (v0 > 20.f) ? v0 : log1pf(__expf(v0));
                        v1 = (v1 > 20.f) ? v1 : log1pf(__expf(v1));
                    } else if (EPI == 2) {
                        v0 = fmaxf(v0, 0.f) + resid[(size_t)rr * N + cc];
                        v1 = fmaxf(v1, 0.f) + resid[(size_t)rr * N + cc + 1];
                    }
                    float2 o; o.x = v0; o.y = v1;
                    *(float2*)(C + (size_t)rr * N + cc) = o;
                }
            }
        }
    }
}

// ---------------------------------------------------------------------------
// Reduce split-K partials for x_dbl
// ---------------------------------------------------------------------------
__global__ void xdbl_reduce_kernel()
{
    int i = blockIdx.x * 256 + threadIdx.x;
    if (i < XPART) {
        float s = g_xpart[i] + g_xpart[i + XPART]
                + g_xpart[i + 2 * XPART] + g_xpart[i + 3 * XPART];
        g_xdbl[i] = s;
    }
}

// ---------------------------------------------------------------------------
// Reduce split-K partials for out-proj + relu + residual (float4)
// ---------------------------------------------------------------------------
__global__ void out_reduce_kernel(const float* __restrict__ resid,
                                  float* __restrict__ out)
{
    int i4 = blockIdx.x * 256 + threadIdx.x;
    if (i4 < OPART / 4) {
        float4 p0 = *(const float4*)(g_opart + (size_t)i4 * 4);
        float4 p1 = *(const float4*)(g_opart + OPART + (size_t)i4 * 4);
        float4 p2 = *(const float4*)(g_opart + 2 * OPART + (size_t)i4 * 4);
        float4 rv = *(const float4*)(resid + (size_t)i4 * 4);
        float4 o;
        o.x = fmaxf(p0.x + p1.x + p2.x, 0.f) + rv.x;
        o.y = fmaxf(p0.y + p1.y + p2.y, 0.f) + rv.y;
        o.z = fmaxf(p0.z + p1.z + p2.z, 0.f) + rv.z;
        o.w = fmaxf(p0.w + p1.w + p2.w, 0.f) + rv.w;
        *(float4*)(out + (size_t)i4 * 4) = o;
    }
}

// ---------------------------------------------------------------------------
// Causal depthwise conv (width 4) + bias + SiLU.
// Each thread: 4 consecutive l x 4 consecutive d, float4 loads (full sectors).
// ---------------------------------------------------------------------------
__global__ void conv_silu_kernel(const float* __restrict__ Wc,
                                 const float* __restrict__ bc)
{
    int gid = blockIdx.x * blockDim.x + threadIdx.x;
    const int D4 = DI_SZ / 4;
    if (gid >= (M_ROWS / 4) * D4) return;
    int d4  = gid % D4;
    int blk = gid / D4;
    int b   = blk / (L_SZ / 4);
    int l0  = (blk % (L_SZ / 4)) * 4;
    int bl0 = b * L_SZ + l0;
    int d   = d4 * 4;

    float4 wq[4];
#pragma unroll
    for (int dd = 0; dd < 4; dd++)
        wq[dd] = *(const float4*)(Wc + (d + dd) * 4);
    float4 bb = *(const float4*)(bc + d);

    float x[7][4];
#pragma unroll
    for (int k = 0; k < 7; k++) {
        int l = l0 - 3 + k;
        if (l >= 0) {
            float4 v = *(const float4*)(g_xz + (size_t)(bl0 - 3 + k) * DI2_SZ + d);
            x[k][0] = v.x; x[k][1] = v.y; x[k][2] = v.z; x[k][3] = v.w;
        } else {
            x[k][0] = x[k][1] = x[k][2] = x[k][3] = 0.f;
        }
    }

    float bias[4] = {bb.x, bb.y, bb.z, bb.w};
#pragma unroll
    for (int i = 0; i < 4; i++) {
        float4 o;
        float* op = (float*)&o;
#pragma unroll
        for (int dd = 0; dd < 4; dd++) {
            float acc = bias[dd];
            acc = fmaf(wq[dd].x, x[i][dd],     acc);
            acc = fmaf(wq[dd].y, x[i + 1][dd], acc);
            acc = fmaf(wq[dd].z, x[i + 2][dd], acc);
            acc = fmaf(wq[dd].w, x[i + 3][dd], acc);
            op[dd] = acc / (1.f + __expf(-acc));
        }
        *(float4*)(g_xc + (size_t)(bl0 + i) * DI_SZ + d) = o;
    }
}

// ---------------------------------------------------------------------------
// Selective scan + skip + gate, 4-step batched (R9/R10 version).
// ---------------------------------------------------------------------------
__global__ __launch_bounds__(256)
void scan_kernel(const float* __restrict__ A_log,
                 const float* __restrict__ Dpar)
{
    int gtid  = blockIdx.x * 256 + threadIdx.x;
    int chain = gtid >> 4;          // 0..6143
    int n     = gtid & 15;
    int b     = chain / DI_SZ;
    int d     = chain % DI_SZ;

    float a  = -__expf(A_log[d * N_ST + n]);
    float dp = Dpar[d];
    float h  = 0.f;
    int base = b * L_SZ;

    const float* pd = g_delta + (size_t)base * DI_SZ + d;
    const float* pu = g_xc    + (size_t)base * DI_SZ + d;
    const float* px = g_xdbl  + (size_t)base * XDBL_W + DTR_SZ + n;
    const float* pz = g_xz    + (size_t)base * DI2_SZ + DI_SZ + d;
    float*       py = g_y     + (size_t)base * DI_SZ + d;

    float dl[4], u[4], Bv[4], Cv[4], z[4];
#pragma unroll
    for (int i = 0; i < 4; i++) {
        dl[i] = pd[i * DI_SZ];
        u[i]  = pu[i * DI_SZ];
        Bv[i] = px[i * XDBL_W];
        Cv[i] = px[i * XDBL_W + N_ST];
        z[i]  = pz[i * DI2_SZ];
    }
    pd += 4 * DI_SZ; pu += 4 * DI_SZ; px += 4 * XDBL_W; pz += 4 * DI2_SZ;

    for (int blk = 0; blk < L_SZ / 4; blk++) {
        float dl2[4], u2[4], Bv2[4], Cv2[4], z2[4];
        if (blk + 1 < L_SZ / 4) {
#pragma unroll
            for (int i = 0; i < 4; i++) {
                dl2[i] = pd[i * DI_SZ];
                u2[i]  = pu[i * DI_SZ];
                Bv2[i] = px[i * XDBL_W];
                Cv2[i] = px[i * XDBL_W + N_ST];
                z2[i]  = pz[i * DI2_SZ];
            }
            pd += 4 * DI_SZ; pu += 4 * DI_SZ; px += 4 * XDBL_W; pz += 4 * DI2_SZ;
        }

        float s0, s1, s2, s3;
        {
            float dA;
            dA = __expf(dl[0] * a); h = fmaf(dA, h, dl[0] * Bv[0] * u[0]); s0 = h * Cv[0];
            dA = __expf(dl[1] * a); h = fmaf(dA, h, dl[1] * Bv[1] * u[1]); s1 = h * Cv[1];
            dA = __expf(dl[2] * a); h = fmaf(dA, h, dl[2] * Bv[2] * u[2]); s2 = h * Cv[2];
            dA = __expf(dl[3] * a); h = fmaf(dA, h, dl[3] * Bv[3] * u[3]); s3 = h * Cv[3];
        }

#pragma unroll
        for (int o = 8; o > 0; o >>= 1) {
            s0 += __shfl_xor_sync(0xffffffffu, s0, o);
            s1 += __shfl_xor_sync(0xffffffffu, s1, o);
            s2 += __shfl_xor_sync(0xffffffffu, s2, o);
            s3 += __shfl_xor_sync(0xffffffffu, s3, o);
        }

        if (n == 0) {
            float sv[4] = {s0, s1, s2, s3};
#pragma unroll
            for (int i = 0; i < 4; i++) {
                float sil = z[i] / (1.f + __expf(-z[i]));
                py[i * DI_SZ] = (sv[i] + u[i] * dp) * sil;
            }
        }
        py += 4 * DI_SZ;

#pragma unroll
        for (int i = 0; i < 4; i++) {
            dl[i] = dl2[i]; u[i] = u2[i]; Bv[i] = Bv2[i]; Cv[i] = Cv2[i]; z[i] = z2[i];
        }
    }
}

// ---------------------------------------------------------------------------
extern "C" void kernel_launch(void* const* d_in, const int* in_sizes, int n_in,
                              void* d_out, int out_size)
{
    const float* input   = (const float*)d_in[0];
    const float* ln_g    = (const float*)d_in[1];
    const float* ln_b    = (const float*)d_in[2];
    const float* W_in    = (const float*)d_in[3];
    const float* W_conv  = (const float*)d_in[4];
    const float* b_conv  = (const float*)d_in[5];
    const float* W_x     = (const float*)d_in[6];
    const float* W_dt    = (const float*)d_in[7];
    const float* b_dt    = (const float*)d_in[8];
    const float* A_log   = (const float*)d_in[9];
    const float* D_param = (const float*)d_in[10];
    const float* W_out   = (const float*)d_in[11];
    float* out = (float*)d_out;

    float *xn, *xz, *xc, *xpart, *xdbl, *delta, *y, *opart;
    cudaGetSymbolAddress((void**)&xn,    g_xn);
    cudaGetSymbolAddress((void**)&xz,    g_xz);
    cudaGetSymbolAddress((void**)&xc,    g_xc);
    cudaGetSymbolAddress((void**)&xpart, g_xpart);
    cudaGetSymbolAddress((void**)&xdbl,  g_xdbl);
    cudaGetSymbolAddress((void**)&delta, g_delta);
    cudaGetSymbolAddress((void**)&y,     g_y);
    cudaGetSymbolAddress((void**)&opart, g_opart);

    cudaFuncSetAttribute(mgemm<0,2>, cudaFuncAttributeMaxDynamicSharedMemorySize, GSMEM);
    cudaFuncSetAttribute(mgemm<1,2>, cudaFuncAttributeMaxDynamicSharedMemorySize, GSMEM);

    // 1. LayerNorm
    ln_kernel<<<M_ROWS, 256>>>(input, ln_g, ln_b);

    // 2. in-proj: xz = xn @ W_in^T   (4096 x 3072 x 768) — 2-pass
    {
        dim3 g(DI2_SZ / 128, M_ROWS / 128, 1);
        mgemm<0,2><<<g, 512, GSMEM>>>(xn, D_SZ, W_in, D_SZ, xz,
                                      M_ROWS, DI2_SZ, D_SZ, nullptr, nullptr, 0);
    }

    // 3. causal depthwise conv + SiLU -> xc (4x4 tiles, float4 loads)
    {
        int total = (M_ROWS / 4) * (DI_SZ / 4);
        conv_silu_kernel<<<(total + 255) / 256, 256>>>(W_conv, b_conv);
    }

    // 4. x_dbl = xc @ W_x^T   (4096 x 80 x 1536) — split-K x4, 2-pass
    {
        dim3 g(1, M_ROWS / 128, KSPLIT);
        mgemm<0,2><<<g, 512, GSMEM>>>(xc, DI_SZ, W_x, DI_SZ, xpart,
                                      M_ROWS, XDBL_W, DI_SZ / KSPLIT,
                                      nullptr, nullptr, (size_t)XPART);
        xdbl_reduce_kernel<<<(XPART + 255) / 256, 256>>>();
    }

    // 5. delta = softplus(dt @ W_dt^T + b_dt)   (4096 x 1536 x 48) — 2-pass
    {
        dim3 g(DI_SZ / 128, M_ROWS / 128, 1);
        mgemm<1,2><<<g, 512, GSMEM>>>(xdbl, XDBL_W, W_dt, DTR_SZ, delta,
                                      M_ROWS, DI_SZ, DTR_SZ, b_dt, nullptr, 0);
    }

    // 6. selective scan + skip + gating -> y
    {
        int threads = B_SZ * DI_SZ * N_ST;   // 98304
        scan_kernel<<<threads / 256, 256>>>(A_log, D_param);
    }

    // 7. out-proj partials: opart[z] = y @ W_out^T slice — split-K x3, 2-pass
    {
        dim3 g(D_SZ / 128, M_ROWS / 128, OSPLIT);
        mgemm<0,2><<<g, 512, GSMEM>>>(y, DI_SZ, W_out, DI_SZ, opart,
                                      M_ROWS, D_SZ, DI_SZ / OSPLIT,
                                      nullptr, nullptr, (size_t)OPART);
        out_reduce_kernel<<<(OPART / 4 + 255) / 256, 256>>>(input, out);
    }
}

// round 17
// speedup vs baseline: 1.7367x; 1.0108x over previous
#include <cuda_runtime.h>
#include <cuda_bf16.h>
#include <math.h>
#include <stdint.h>

// Problem constants
#define B_SZ   4
#define L_SZ   1024
#define D_SZ   768
#define DI_SZ  1536
#define DI2_SZ 3072
#define N_ST   16
#define DTR_SZ 48
#define XDBL_W 80           // DTR + 2*N
#define M_ROWS 4096         // B*L
#define KSPLIT 4
#define XPART  (M_ROWS * XDBL_W)
#define OSPLIT 3
#define OPART  (M_ROWS * D_SZ)

// Scratch (device globals; no allocation allowed)
__device__ float g_xn  [M_ROWS * D_SZ];
__device__ float g_xz  [M_ROWS * DI2_SZ];
__device__ float g_xc  [M_ROWS * DI_SZ];
__device__ float g_xpart[KSPLIT * XPART];
__device__ float g_xdbl[M_ROWS * XDBL_W];
__device__ float g_delta[M_ROWS * DI_SZ];
__device__ float g_y   [M_ROWS * DI_SZ];
__device__ float g_opart[OSPLIT * OPART];

__device__ __forceinline__ void mma16(float* d,
                                      const uint32_t* a, const uint32_t* b) {
    asm volatile(
        "mma.sync.aligned.m16n8k16.row.col.f32.bf16.bf16.f32 "
        "{%0,%1,%2,%3}, {%4,%5,%6,%7}, {%8,%9}, {%0,%1,%2,%3};"
        : "+f"(d[0]), "+f"(d[1]), "+f"(d[2]), "+f"(d[3])
        : "r"(a[0]), "r"(a[1]), "r"(a[2]), "r"(a[3]), "r"(b[0]), "r"(b[1]));
}

__device__ __forceinline__ void ldsm4(uint32_t& r0, uint32_t& r1,
                                      uint32_t& r2, uint32_t& r3, uint32_t a) {
    asm volatile("ldmatrix.sync.aligned.m8n8.x4.shared.b16 {%0,%1,%2,%3}, [%4];"
                 : "=r"(r0), "=r"(r1), "=r"(r2), "=r"(r3) : "r"(a));
}

__device__ __forceinline__ uint32_t s2u(const void* p) {
    uint32_t a;
    asm("{ .reg .u64 t; cvta.to.shared.u64 t, %1; cvt.u32.u64 %0, t; }"
        : "=r"(a) : "l"(p));
    return a;
}

// split float4 into 4x bf16 hi (8B) and 4x bf16 lo (8B)
__device__ __forceinline__ void split4(float4 v, uint2& h, uint2& l) {
    __nv_bfloat16 hx = __float2bfloat16_rn(v.x);
    __nv_bfloat16 hy = __float2bfloat16_rn(v.y);
    __nv_bfloat16 hz = __float2bfloat16_rn(v.z);
    __nv_bfloat16 hw = __float2bfloat16_rn(v.w);
    __nv_bfloat162 h0 = __halves2bfloat162(hx, hy);
    __nv_bfloat162 h1 = __halves2bfloat162(hz, hw);
    __nv_bfloat162 l0 = __halves2bfloat162(
        __float2bfloat16_rn(v.x - __bfloat162float(hx)),
        __float2bfloat16_rn(v.y - __bfloat162float(hy)));
    __nv_bfloat162 l1 = __halves2bfloat162(
        __float2bfloat16_rn(v.z - __bfloat162float(hz)),
        __float2bfloat16_rn(v.w - __bfloat162float(hw)));
    h.x = *(uint32_t*)&h0; h.y = *(uint32_t*)&h1;
    l.x = *(uint32_t*)&l0; l.y = *(uint32_t*)&l1;
}

// hi-only pack: float4 -> 4x bf16 (8B)
__device__ __forceinline__ uint2 hi4(float4 v) {
    __nv_bfloat162 h0 = __floats2bfloat162_rn(v.x, v.y);
    __nv_bfloat162 h1 = __floats2bfloat162_rn(v.z, v.w);
    uint2 r;
    r.x = *(uint32_t*)&h0; r.y = *(uint32_t*)&h1;
    return r;
}

// ---------------------------------------------------------------------------
// LayerNorm: one block (256 thr) per row of 768
// ---------------------------------------------------------------------------
__global__ void ln_kernel(const float* __restrict__ x,
                          const float* __restrict__ gam,
                          const float* __restrict__ bet)
{
    int row = blockIdx.x;
    const float* xr = x + (size_t)row * D_SZ;
    float v[3];
    float s = 0.f, sq = 0.f;
#pragma unroll
    for (int i = 0; i < 3; i++) {
        v[i] = xr[threadIdx.x + i * 256];
        s += v[i];
        sq += v[i] * v[i];
    }
#pragma unroll
    for (int o = 16; o > 0; o >>= 1) {
        s  += __shfl_xor_sync(0xffffffffu, s, o);
        sq += __shfl_xor_sync(0xffffffffu, sq, o);
    }
    __shared__ float ss[8], ssq[8];
    int w = threadIdx.x >> 5, lane = threadIdx.x & 31;
    if (lane == 0) { ss[w] = s; ssq[w] = sq; }
    __syncthreads();
    if (w == 0) {
        s  = (lane < 8) ? ss[lane]  : 0.f;
        sq = (lane < 8) ? ssq[lane] : 0.f;
#pragma unroll
        for (int o = 4; o > 0; o >>= 1) {
            s  += __shfl_xor_sync(0xffffffffu, s, o);
            sq += __shfl_xor_sync(0xffffffffu, sq, o);
        }
        if (lane == 0) { ss[0] = s; ssq[0] = sq; }
    }
    __syncthreads();
    float mu  = ss[0] * (1.f / D_SZ);
    float var = ssq[0] * (1.f / D_SZ) - mu * mu;
    float rs  = rsqrtf(var + 1e-6f);
#pragma unroll
    for (int i = 0; i < 3; i++) {
        int c = threadIdx.x + i * 256;
        g_xn[(size_t)row * D_SZ + c] = (v[i] - mu) * rs * gam[c] + bet[c];
    }
}

// ---------------------------------------------------------------------------
// bf16-split NT GEMM: inline f32->bf16 hi/lo split at STS, ldmatrix mainloop.
// Tile 128x128x32, 512 threads (16 warps 4x4), warp tile 32x32.
// Split-K via gridDim.z: both A and B advance by z*K columns.
// NPASS=2: hi*hi + lo*hi     NPASS=1: hi*hi only (pure bf16)
// EPI 0: plain   EPI 1: softplus(acc + bias[n])
// ---------------------------------------------------------------------------
#define RSB    80                 // smem bytes per row (64 data + 16 pad)
#define TILEB  (128 * RSB)        // 10240
#define STAGEB (4 * TILEB)        // 40960
#define GSMEM  (2 * STAGEB)       // 81920

template <int EPI, int NPASS>
__global__ __launch_bounds__(512)
void mgemm(const float* __restrict__ A, int lda,
           const float* __restrict__ Bm, int ldb,
           float* __restrict__ C, int M, int N, int K,
           const float* __restrict__ bias,
           const float* __restrict__ resid, size_t zC)
{
    extern __shared__ __align__(16) char smraw[];
    uint32_t smbase = s2u(smraw);

    A  += (size_t)blockIdx.z * K;
    Bm += (size_t)blockIdx.z * K;
    C  += (size_t)blockIdx.z * zC;

    int tid = threadIdx.x;
    int wid = tid >> 5, lane = tid & 31;
    int wm = (wid & 3) * 32;
    int wn = (wid >> 2) * 32;
    int grp = lane >> 2, qd = lane & 3;
    int row0 = blockIdx.y * 128, col0 = blockIdx.x * 128;

    float acc[2][4][4];
#pragma unroll
    for (int mi = 0; mi < 2; mi++)
#pragma unroll
        for (int ni = 0; ni < 4; ni++)
#pragma unroll
            for (int e = 0; e < 4; e++) acc[mi][ni][e] = 0.f;

    const int nch = (K + 31) / 32;

    int lrow = tid >> 2;           // 0..127
    int q    = tid & 3;            // float4 slot pair

    float4 pa[2], pb[2];

    auto loadc = [&](int c) {
        int kc = c * 32;
#pragma unroll
        for (int j = 0; j < 2; j++) {
            int col = kc + q * 8 + j * 4;
            bool kok = col < K;
            pa[j] = kok ? *(const float4*)(A + (size_t)(row0 + lrow) * lda + col)
                        : make_float4(0.f, 0.f, 0.f, 0.f);
            int n = col0 + lrow;
            pb[j] = (kok && n < N) ? *(const float4*)(Bm + (size_t)n * ldb + col)
                                   : make_float4(0.f, 0.f, 0.f, 0.f);
        }
    };

    auto storec = [&](int s) {
        uint32_t st = smbase + (uint32_t)s * STAGEB + lrow * RSB;
#pragma unroll
        for (int j = 0; j < 2; j++) {
            uint32_t co = (q * 8 + j * 4) * 2;
            if (NPASS >= 2) {
                uint2 h, l;
                split4(pa[j], h, l);
                *(uint2*)(smraw + (st - smbase) + co)         = h;
                *(uint2*)(smraw + (st - smbase) + TILEB + co) = l;
            } else {
                *(uint2*)(smraw + (st - smbase) + co) = hi4(pa[j]);
            }
            *(uint2*)(smraw + (st - smbase) + 2 * TILEB + co) = hi4(pb[j]);
        }
    };

    loadc(0);
    storec(0);
    __syncthreads();

    int arow = lane & 15;
    int asel = (lane >> 4) * 16;
    int brow = ((lane >> 4) << 3) + (lane & 7);
    int bsel = ((lane >> 3) & 1) * 16;

    for (int c = 0; c < nch; c++) {
        int s = c & 1;
        if (c + 1 < nch) loadc(c + 1);

        uint32_t stA  = smbase + (uint32_t)s * STAGEB;
        uint32_t stAl = stA + TILEB;
        uint32_t stB  = stA + 2 * TILEB;

#pragma unroll
        for (int ks = 0; ks < 2; ks++) {
            int kb = ks * 32;   // byte offset of k-half
            uint32_t ahi[2][4], alo[2][4], bhi[4][2];
#pragma unroll
            for (int mi = 0; mi < 2; mi++) {
                uint32_t ad = stA + (wm + mi * 16 + arow) * RSB + kb + asel;
                ldsm4(ahi[mi][0], ahi[mi][1], ahi[mi][2], ahi[mi][3], ad);
            }
#pragma unroll
            for (int nb = 0; nb < 2; nb++) {
                uint32_t bd = stB + (wn + nb * 16 + brow) * RSB + kb + bsel;
                ldsm4(bhi[2 * nb][0], bhi[2 * nb][1],
                      bhi[2 * nb + 1][0], bhi[2 * nb + 1][1], bd);
            }
            // pass 1: hi*hi
#pragma unroll
            for (int mi = 0; mi < 2; mi++)
#pragma unroll
                for (int ni = 0; ni < 4; ni++)
                    mma16(acc[mi][ni], ahi[mi], bhi[ni]);
            // pass 2: lo*hi
            if (NPASS >= 2) {
#pragma unroll
                for (int mi = 0; mi < 2; mi++) {
                    uint32_t ad = stAl + (wm + mi * 16 + arow) * RSB + kb + asel;
                    ldsm4(alo[mi][0], alo[mi][1], alo[mi][2], alo[mi][3], ad);
                }
#pragma unroll
                for (int mi = 0; mi < 2; mi++)
#pragma unroll
                    for (int ni = 0; ni < 4; ni++)
                        mma16(acc[mi][ni], alo[mi], bhi[ni]);
            }
        }

        if (c + 1 < nch) storec((c + 1) & 1);
        __syncthreads();
    }

    // epilogue: registers -> gmem
#pragma unroll
    for (int mi = 0; mi < 2; mi++) {
#pragma unroll
        for (int ni = 0; ni < 4; ni++) {
            int r  = row0 + wm + mi * 16 + grp;
            int cc = col0 + wn + ni * 8 + qd * 2;
            if (cc < N) {
#pragma unroll
                for (int h = 0; h < 2; h++) {
                    int rr = r + h * 8;
                    float v0 = acc[mi][ni][h * 2 + 0];
                    float v1 = acc[mi][ni][h * 2 + 1];
                    if (EPI == 1) {
                        v0 += bias[cc];
                        v1 += bias[cc + 1];
                        v0 = (v0 > 20.f) ? v0 : log1pf(__expf(v0));
                        v1 = (v1 > 20.f) ? v1 : log1pf(__expf(v1));
                    }
                    float2 o; o.x = v0; o.y = v1;
                    *(float2*)(C + (size_t)rr * N + cc) = o;
                }
            }
        }
    }
}

// ---------------------------------------------------------------------------
// Reduce split-K partials for x_dbl
// ---------------------------------------------------------------------------
__global__ void xdbl_reduce_kernel()
{
    int i = blockIdx.x * 256 + threadIdx.x;
    if (i < XPART) {
        float s = g_xpart[i] + g_xpart[i + XPART]
                + g_xpart[i + 2 * XPART] + g_xpart[i + 3 * XPART];
        g_xdbl[i] = s;
    }
}

// ---------------------------------------------------------------------------
// Reduce split-K partials for out-proj + relu + residual (float4)
// ---------------------------------------------------------------------------
__global__ void out_reduce_kernel(const float* __restrict__ resid,
                                  float* __restrict__ out)
{
    int i4 = blockIdx.x * 256 + threadIdx.x;
    if (i4 < OPART / 4) {
        float4 p0 = *(const float4*)(g_opart + (size_t)i4 * 4);
        float4 p1 = *(const float4*)(g_opart + OPART + (size_t)i4 * 4);
        float4 p2 = *(const float4*)(g_opart + 2 * OPART + (size_t)i4 * 4);
        float4 rv = *(const float4*)(resid + (size_t)i4 * 4);
        float4 o;
        o.x = fmaxf(p0.x + p1.x + p2.x, 0.f) + rv.x;
        o.y = fmaxf(p0.y + p1.y + p2.y, 0.f) + rv.y;
        o.z = fmaxf(p0.z + p1.z + p2.z, 0.f) + rv.z;
        o.w = fmaxf(p0.w + p1.w + p2.w, 0.f) + rv.w;
        *(float4*)(out + (size_t)i4 * 4) = o;
    }
}

// ---------------------------------------------------------------------------
// Causal depthwise conv (width 4) + bias + SiLU.
// Each thread: 4 consecutive l x 4 consecutive d, float4 loads (full sectors).
// ---------------------------------------------------------------------------
__global__ void conv_silu_kernel(const float* __restrict__ Wc,
                                 const float* __restrict__ bc)
{
    int gid = blockIdx.x * blockDim.x + threadIdx.x;
    const int D4 = DI_SZ / 4;
    if (gid >= (M_ROWS / 4) * D4) return;
    int d4  = gid % D4;
    int blk = gid / D4;
    int b   = blk / (L_SZ / 4);
    int l0  = (blk % (L_SZ / 4)) * 4;
    int bl0 = b * L_SZ + l0;
    int d   = d4 * 4;

    float4 wq[4];
#pragma unroll
    for (int dd = 0; dd < 4; dd++)
        wq[dd] = *(const float4*)(Wc + (d + dd) * 4);
    float4 bb = *(const float4*)(bc + d);

    float x[7][4];
#pragma unroll
    for (int k = 0; k < 7; k++) {
        int l = l0 - 3 + k;
        if (l >= 0) {
            float4 v = *(const float4*)(g_xz + (size_t)(bl0 - 3 + k) * DI2_SZ + d);
            x[k][0] = v.x; x[k][1] = v.y; x[k][2] = v.z; x[k][3] = v.w;
        } else {
            x[k][0] = x[k][1] = x[k][2] = x[k][3] = 0.f;
        }
    }

    float bias[4] = {bb.x, bb.y, bb.z, bb.w};
#pragma unroll
    for (int i = 0; i < 4; i++) {
        float4 o;
        float* op = (float*)&o;
#pragma unroll
        for (int dd = 0; dd < 4; dd++) {
            float acc = bias[dd];
            acc = fmaf(wq[dd].x, x[i][dd],     acc);
            acc = fmaf(wq[dd].y, x[i + 1][dd], acc);
            acc = fmaf(wq[dd].z, x[i + 2][dd], acc);
            acc = fmaf(wq[dd].w, x[i + 3][dd], acc);
            op[dd] = acc / (1.f + __expf(-acc));
        }
        *(float4*)(g_xc + (size_t)(bl0 + i) * DI_SZ + d) = o;
    }
}

// ---------------------------------------------------------------------------
// Selective scan + skip + gate, 4-step batched; z load predicated to lane 0.
// ---------------------------------------------------------------------------
__global__ __launch_bounds__(256)
void scan_kernel(const float* __restrict__ A_log,
                 const float* __restrict__ Dpar)
{
    int gtid  = blockIdx.x * 256 + threadIdx.x;
    int chain = gtid >> 4;          // 0..6143
    int n     = gtid & 15;
    int b     = chain / DI_SZ;
    int d     = chain % DI_SZ;
    bool lead = (n == 0);

    float a  = -__expf(A_log[d * N_ST + n]);
    float dp = Dpar[d];
    float h  = 0.f;
    int base = b * L_SZ;

    const float* pd = g_delta + (size_t)base * DI_SZ + d;
    const float* pu = g_xc    + (size_t)base * DI_SZ + d;
    const float* px = g_xdbl  + (size_t)base * XDBL_W + DTR_SZ + n;
    const float* pz = g_xz    + (size_t)base * DI2_SZ + DI_SZ + d;
    float*       py = g_y     + (size_t)base * DI_SZ + d;

    float dl[4], u[4], Bv[4], Cv[4], z[4];
#pragma unroll
    for (int i = 0; i < 4; i++) {
        dl[i] = pd[i * DI_SZ];
        u[i]  = pu[i * DI_SZ];
        Bv[i] = px[i * XDBL_W];
        Cv[i] = px[i * XDBL_W + N_ST];
        z[i]  = lead ? pz[i * DI2_SZ] : 0.f;
    }
    pd += 4 * DI_SZ; pu += 4 * DI_SZ; px += 4 * XDBL_W; pz += 4 * DI2_SZ;

    for (int blk = 0; blk < L_SZ / 4; blk++) {
        float dl2[4], u2[4], Bv2[4], Cv2[4], z2[4];
        if (blk + 1 < L_SZ / 4) {
#pragma unroll
            for (int i = 0; i < 4; i++) {
                dl2[i] = pd[i * DI_SZ];
                u2[i]  = pu[i * DI_SZ];
                Bv2[i] = px[i * XDBL_W];
                Cv2[i] = px[i * XDBL_W + N_ST];
                z2[i]  = lead ? pz[i * DI2_SZ] : 0.f;
            }
            pd += 4 * DI_SZ; pu += 4 * DI_SZ; px += 4 * XDBL_W; pz += 4 * DI2_SZ;
        }

        float s0, s1, s2, s3;
        {
            float dA;
            dA = __expf(dl[0] * a); h = fmaf(dA, h, dl[0] * Bv[0] * u[0]); s0 = h * Cv[0];
            dA = __expf(dl[1] * a); h = fmaf(dA, h, dl[1] * Bv[1] * u[1]); s1 = h * Cv[1];
            dA = __expf(dl[2] * a); h = fmaf(dA, h, dl[2] * Bv[2] * u[2]); s2 = h * Cv[2];
            dA = __expf(dl[3] * a); h = fmaf(dA, h, dl[3] * Bv[3] * u[3]); s3 = h * Cv[3];
        }

#pragma unroll
        for (int o = 8; o > 0; o >>= 1) {
            s0 += __shfl_xor_sync(0xffffffffu, s0, o);
            s1 += __shfl_xor_sync(0xffffffffu, s1, o);
            s2 += __shfl_xor_sync(0xffffffffu, s2, o);
            s3 += __shfl_xor_sync(0xffffffffu, s3, o);
        }

        if (lead) {
            float sv[4] = {s0, s1, s2, s3};
#pragma unroll
            for (int i = 0; i < 4; i++) {
                float sil = z[i] / (1.f + __expf(-z[i]));
                py[i * DI_SZ] = (sv[i] + u[i] * dp) * sil;
            }
        }
        py += 4 * DI_SZ;

#pragma unroll
        for (int i = 0; i < 4; i++) {
            dl[i] = dl2[i]; u[i] = u2[i]; Bv[i] = Bv2[i]; Cv[i] = Cv2[i]; z[i] = z2[i];
        }
    }
}

// ---------------------------------------------------------------------------
extern "C" void kernel_launch(void* const* d_in, const int* in_sizes, int n_in,
                              void* d_out, int out_size)
{
    const float* input   = (const float*)d_in[0];
    const float* ln_g    = (const float*)d_in[1];
    const float* ln_b    = (const float*)d_in[2];
    const float* W_in    = (const float*)d_in[3];
    const float* W_conv  = (const float*)d_in[4];
    const float* b_conv  = (const float*)d_in[5];
    const float* W_x     = (const float*)d_in[6];
    const float* W_dt    = (const float*)d_in[7];
    const float* b_dt    = (const float*)d_in[8];
    const float* A_log   = (const float*)d_in[9];
    const float* D_param = (const float*)d_in[10];
    const float* W_out   = (const float*)d_in[11];
    float* out = (float*)d_out;

    float *xn, *xz, *xc, *xpart, *xdbl, *delta, *y, *opart;
    cudaGetSymbolAddress((void**)&xn,    g_xn);
    cudaGetSymbolAddress((void**)&xz,    g_xz);
    cudaGetSymbolAddress((void**)&xc,    g_xc);
    cudaGetSymbolAddress((void**)&xpart, g_xpart);
    cudaGetSymbolAddress((void**)&xdbl,  g_xdbl);
    cudaGetSymbolAddress((void**)&delta, g_delta);
    cudaGetSymbolAddress((void**)&y,     g_y);
    cudaGetSymbolAddress((void**)&opart, g_opart);

    cudaFuncSetAttribute(mgemm<0,2>, cudaFuncAttributeMaxDynamicSharedMemorySize, GSMEM);
    cudaFuncSetAttribute(mgemm<0,1>, cudaFuncAttributeMaxDynamicSharedMemorySize, GSMEM);
    cudaFuncSetAttribute(mgemm<1,1>, cudaFuncAttributeMaxDynamicSharedMemorySize, GSMEM);

    // 1. LayerNorm
    ln_kernel<<<M_ROWS, 256>>>(input, ln_g, ln_b);

    // 2. in-proj: xz = xn @ W_in^T   (4096 x 3072 x 768) — 2-pass
    {
        dim3 g(DI2_SZ / 128, M_ROWS / 128, 1);
        mgemm<0,2><<<g, 512, GSMEM>>>(xn, D_SZ, W_in, D_SZ, xz,
                                      M_ROWS, DI2_SZ, D_SZ, nullptr, nullptr, 0);
    }

    // 3. causal depthwise conv + SiLU -> xc (4x4 tiles, float4 loads)
    {
        int total = (M_ROWS / 4) * (DI_SZ / 4);
        conv_silu_kernel<<<(total + 255) / 256, 256>>>(W_conv, b_conv);
    }

    // 4. x_dbl = xc @ W_x^T   (4096 x 80 x 1536) — split-K x4, 1-pass
    {
        dim3 g(1, M_ROWS / 128, KSPLIT);
        mgemm<0,1><<<g, 512, GSMEM>>>(xc, DI_SZ, W_x, DI_SZ, xpart,
                                      M_ROWS, XDBL_W, DI_SZ / KSPLIT,
                                      nullptr, nullptr, (size_t)XPART);
        xdbl_reduce_kernel<<<(XPART + 255) / 256, 256>>>();
    }

    // 5. delta = softplus(dt @ W_dt^T + b_dt)   (4096 x 1536 x 48) — 1-pass
    {
        dim3 g(DI_SZ / 128, M_ROWS / 128, 1);
        mgemm<1,1><<<g, 512, GSMEM>>>(xdbl, XDBL_W, W_dt, DTR_SZ, delta,
                                      M_ROWS, DI_SZ, DTR_SZ, b_dt, nullptr, 0);
    }

    // 6. selective scan + skip + gating -> y
    {
        int threads = B_SZ * DI_SZ * N_ST;   // 98304
        scan_kernel<<<threads / 256, 256>>>(A_log, D_param);
    }

    // 7. out-proj partials: opart[z] = y @ W_out^T slice — split-K x3, 2-pass
    {
        dim3 g(D_SZ / 128, M_ROWS / 128, OSPLIT);
        mgemm<0,2><<<g, 512, GSMEM>>>(y, DI_SZ, W_out, DI_SZ, opart,
                                      M_ROWS, D_SZ, DI_SZ / OSPLIT,
                                      nullptr, nullptr, (size_t)OPART);
        out_reduce_kernel<<<(OPART / 4 + 255) / 256, 256>>>(input, out);
    }
}